// round 7
// baseline (speedup 1.0000x reference)
#include <cuda_runtime.h>
#include <cuda_bf16.h>
#include <cstdint>

#define NN   50000
#define EE   600000
#define DD   128
#define DOUT 64
#define NB   ((NN + 255) / 256)   // 196

// ---------------- scratch ----------------
__device__ float g_mA[(size_t)NN * DD];
__device__ float g_mB[(size_t)NN * DD];
__device__ __nv_bfloat16 g_w1h[DD * DD], g_w1l[DD * DD];
__device__ __nv_bfloat16 g_w2h[DD * DD], g_w2l[DD * DD];
__device__ __nv_bfloat16 g_woh[DOUT * DD], g_wol[DOUT * DD];
__device__ int g_deg[NN], g_cnt[NN], g_off[NN + 1];
__device__ int g_part[NB], g_poff[NB];
__device__ int g_csr[EE];
__device__ int g_is64;

__device__ __forceinline__ uint32_t smem_u32(const void* p) {
    uint32_t a;
    asm("{ .reg .u64 t; cvta.to.shared.u64 t, %1; cvt.u32.u64 %0, t; }" : "=r"(a) : "l"(p));
    return a;
}

__device__ __forceinline__ int edge_idx(const void* ei, int which, int e) {
    if (g_is64) return (int)((const long long*)ei)[(size_t)which * EE + e];
    return ((const int*)ei)[which * EE + e];
}

// ---------------- CSR build (side stream) ----------------
__global__ void zero_detect_kernel(const unsigned int* __restrict__ w) {
    int i = blockIdx.x * blockDim.x + threadIdx.x;
    if (i < NN) { g_deg[i] = 0; g_cnt[i] = 0; }
    if (i == 0) {
        int is64 = 1;
        for (int j = 1; j < 128; j += 2)
            if (w[j] != 0u) { is64 = 0; break; }
        g_is64 = is64;
    }
}
__global__ void hist_kernel(const void* ei) {
    int e = blockIdx.x * blockDim.x + threadIdx.x;
    if (e < EE) atomicAdd(&g_deg[edge_idx(ei, 1, e)], 1);
}
__global__ void partial_kernel() {
    __shared__ int sh[256];
    int t = threadIdx.x, i = blockIdx.x * 256 + t;
    sh[t] = (i < NN) ? g_deg[i] : 0;
    __syncthreads();
    for (int d = 128; d > 0; d >>= 1) {
        if (t < d) sh[t] += sh[t + d];
        __syncthreads();
    }
    if (t == 0) g_part[blockIdx.x] = sh[0];
}
__global__ void scanpart_kernel() {
    __shared__ int sh[256];
    int t = threadIdx.x;
    int v = (t < NB) ? g_part[t] : 0;
    sh[t] = v;
    __syncthreads();
    for (int d = 1; d < 256; d <<= 1) {
        int u = (t >= d) ? sh[t - d] : 0;
        __syncthreads();
        sh[t] += u;
        __syncthreads();
    }
    if (t < NB) g_poff[t] = sh[t] - v;
    if (t == 0) g_off[NN] = EE;
}
__global__ void offs_kernel() {
    __shared__ int sh[256];
    int t = threadIdx.x, i = blockIdx.x * 256 + t;
    int v = (i < NN) ? g_deg[i] : 0;
    sh[t] = v;
    __syncthreads();
    for (int d = 1; d < 256; d <<= 1) {
        int u = (t >= d) ? sh[t - d] : 0;
        __syncthreads();
        sh[t] += u;
        __syncthreads();
    }
    if (i < NN) g_off[i] = g_poff[blockIdx.x] + sh[t] - v;
}
__global__ void fill_kernel(const void* ei) {
    int e = blockIdx.x * blockDim.x + threadIdx.x;
    if (e < EE) {
        int d = edge_idx(ei, 1, e);
        int s = edge_idx(ei, 0, e);
        g_csr[g_off[d] + atomicAdd(&g_cnt[d], 1)] = s;
    }
}

// ---------------- split helpers ----------------
__device__ __forceinline__ void split2(float x, __nv_bfloat16& h, __nv_bfloat16& l) {
    h = __float2bfloat16(x);
    l = __float2bfloat16(x - __bfloat162float(h));
}

__global__ void tw_all_kernel(const float* __restrict__ W1, const float* __restrict__ W2,
                              const float* __restrict__ Wo) {
    int i = blockIdx.x * blockDim.x + threadIdx.x;
    if (i < 16384) {
        int n = i >> 7, k = i & 127;
        split2(W1[k * DD + n], g_w1h[i], g_w1l[i]);
    } else if (i < 32768) {
        int j = i - 16384;
        int n = j >> 7, k = j & 127;
        split2(W2[k * DD + n], g_w2h[j], g_w2l[j]);
    } else if (i < 32768 + DOUT * DD) {
        int j = i - 32768;
        int n = j >> 7, k = j & 127;
        split2(Wo[k * DOUT + n], g_woh[j], g_wol[j]);
    }
}

// ======================================================================
// fused pool kernel: per 64-node tile, edge-parallel gather into smem
// fp32 accumulators, then split-bf16 3-pass MMA, write Mout.
// 512 threads, 2 CTAs/SM.
// smem layout (bytes):
//   [0, 512)            s_off (65 ints)
//   [512, 33280)        ACC: 64 rows x 128 fp32 (row stride 512 B)
//   [33280, 49664)      AHI: 64 rows x 256 B (swizzled bf16)
//   [49664, 66048)      ALO
//   [66048, 66048+N*256) B plane (swizzled bf16, restaged)
// ======================================================================
template <int N, int RELU>
__global__ void __launch_bounds__(512, 2) pool_fused(
    const float* __restrict__ Min,
    const __nv_bfloat16* __restrict__ Bhi, const __nv_bfloat16* __restrict__ Blo,
    const float* __restrict__ bias, float* __restrict__ Mout)
{
    extern __shared__ char smem[];
    constexpr int SOFF = 0, ACC = 512, AHI = 33280, ALO = 49664, BOFF = 66048;
    uint32_t sb = smem_u32(smem);
    int tid = threadIdx.x, wid = tid >> 5, lane = tid & 31;
    int row0 = blockIdx.x * 64;
    int nvalid = min(64, NN - row0);

    int* soff = (int*)(smem + SOFF);
    float* accs = (float*)(smem + ACC);

    // load tile offsets
    if (tid <= nvalid) soff[tid] = g_off[row0 + tid];
    // zero ACC
    for (int i = tid; i < 64 * 128 / 4; i += 512)
        ((float4*)accs)[i] = make_float4(0.f, 0.f, 0.f, 0.f);
    // stage B hi (overlaps with gather-phase memory traffic setup)
    for (int idx = tid; idx < N * 16; idx += 512) {
        int r = idx >> 4, ch = idx & 15;
        uint4 v = *(const uint4*)(Bhi + r * DD + ch * 8);
        *(uint4*)(smem + BOFF + r * 256 + ((ch ^ (r & 7)) << 4)) = v;
    }
    __syncthreads();

    // ---------- gather phase: edge-parallel segmented sum ----------
    {
        int tbeg = soff[0], tend = soff[nvalid];
        int total = tend - tbeg;
        int wbeg = tbeg + (int)(((long long)total * wid) >> 4);
        int wend = tbeg + (int)(((long long)total * (wid + 1)) >> 4);
        if (wbeg < wend) {
            // binary search: node with soff[node] <= wbeg < soff[node+1]
            int lo = 0, hi = nvalid - 1;
            while (lo < hi) {
                int mid = (lo + hi + 1) >> 1;
                if (soff[mid] <= wbeg) lo = mid; else hi = mid - 1;
            }
            int node = lo;
            const float4* base = (const float4*)Min;
            float4 racc = make_float4(0.f, 0.f, 0.f, 0.f);
            int dirty = 0;
            int e = wbeg;
            while (e < wend) {
                int nb = wend - e;
                if (nb > 8) nb = 8;
                int src[8];
                float4 v[8];
#pragma unroll
                for (int i = 0; i < 8; i++)
                    if (i < nb) src[i] = g_csr[e + i];
#pragma unroll
                for (int i = 0; i < 8; i++)
                    if (i < nb) v[i] = base[src[i] * 32 + lane];
#pragma unroll
                for (int i = 0; i < 8; i++) {
                    if (i < nb) {
                        while (e + i >= soff[node + 1]) {
                            if (dirty) {
                                float* a = accs + node * 128 + lane * 4;
                                atomicAdd(a + 0, racc.x);
                                atomicAdd(a + 1, racc.y);
                                atomicAdd(a + 2, racc.z);
                                atomicAdd(a + 3, racc.w);
                                racc = make_float4(0.f, 0.f, 0.f, 0.f);
                                dirty = 0;
                            }
                            node++;
                        }
                        racc.x += v[i].x; racc.y += v[i].y;
                        racc.z += v[i].z; racc.w += v[i].w;
                        dirty = 1;
                    }
                }
                e += nb;
            }
            if (dirty) {
                float* a = accs + node * 128 + lane * 4;
                atomicAdd(a + 0, racc.x);
                atomicAdd(a + 1, racc.y);
                atomicAdd(a + 2, racc.z);
                atomicAdd(a + 3, racc.w);
            }
        }
    }
    __syncthreads();

    // ---------- split ACC -> AHI/ALO (with optional relu) ----------
    for (int idx = tid; idx < 64 * 16; idx += 512) {
        int r = idx >> 4, ch = idx & 15;
        const float* p = accs + r * 128 + ch * 8;
        __nv_bfloat16 h[8], l[8];
#pragma unroll
        for (int j = 0; j < 8; j++) {
            float f = p[j];
            if (RELU) f = fmaxf(f, 0.f);
            split2(f, h[j], l[j]);
        }
        int off = r * 256 + ((ch ^ (r & 7)) << 4);
        *(uint4*)(smem + AHI + off) = *(uint4*)h;
        *(uint4*)(smem + ALO + off) = *(uint4*)l;
    }
    __syncthreads();

    // ---------- MMA: 16 warps ----------
    constexpr int WRN = (N == 128) ? 2 : 4;   // row-warp groups
    constexpr int MF  = (N == 128) ? 2 : 1;   // 16-row fragments per warp
    int wr = wid % WRN, wc = wid / WRN;       // wc covers 16 cols each
    int lr = lane & 7;
    int a_half = (lane >> 3) & 1, a_kc = lane >> 4;
    int b_kc = (lane >> 3) & 1, b_nh = lane >> 4;
    uint32_t a_rb[MF];
#pragma unroll
    for (int mf = 0; mf < MF; mf++)
        a_rb[mf] = (uint32_t)((wr * MF * 16 + mf * 16 + a_half * 8 + lr) * 256);
    uint32_t b_rb = (uint32_t)((wc * 16 + b_nh * 8 + lr) * 256);

    float acc[MF * 2][4];
#pragma unroll
    for (int i = 0; i < MF * 2; i++)
#pragma unroll
        for (int j = 0; j < 4; j++) acc[i][j] = 0.f;

    // passes: 0 = Ahi*Bhi, 1 = Alo*Bhi, (restage Blo), 2 = Ahi*Blo
#pragma unroll
    for (int p = 0; p < 3; p++) {
        uint32_t Ab = sb + (uint32_t)((p == 1) ? ALO : AHI);
        uint32_t Bb = sb + (uint32_t)BOFF;
#pragma unroll
        for (int ks = 0; ks < 8; ks++) {
            int c0 = ks * 2;
            uint32_t a[MF][4];
#pragma unroll
            for (int mf = 0; mf < MF; mf++) {
                uint32_t addr = Ab + a_rb[mf] + (uint32_t)(((c0 + a_kc) ^ lr) << 4);
                asm volatile("ldmatrix.sync.aligned.m8n8.x4.shared.b16 {%0,%1,%2,%3}, [%4];"
                    : "=r"(a[mf][0]), "=r"(a[mf][1]), "=r"(a[mf][2]), "=r"(a[mf][3]) : "r"(addr));
            }
            uint32_t addr = Bb + b_rb + (uint32_t)(((c0 + b_kc) ^ lr) << 4);
            uint32_t b0, b1, b2, b3;
            asm volatile("ldmatrix.sync.aligned.m8n8.x4.shared.b16 {%0,%1,%2,%3}, [%4];"
                : "=r"(b0), "=r"(b1), "=r"(b2), "=r"(b3) : "r"(addr));
#pragma unroll
            for (int mf = 0; mf < MF; mf++) {
                float* c = acc[mf * 2];
                asm volatile("mma.sync.aligned.m16n8k16.row.col.f32.bf16.bf16.f32 "
                    "{%0,%1,%2,%3}, {%4,%5,%6,%7}, {%8,%9}, {%0,%1,%2,%3};"
                    : "+f"(c[0]), "+f"(c[1]), "+f"(c[2]), "+f"(c[3])
                    : "r"(a[mf][0]), "r"(a[mf][1]), "r"(a[mf][2]), "r"(a[mf][3]), "r"(b0), "r"(b1));
                float* d = acc[mf * 2 + 1];
                asm volatile("mma.sync.aligned.m16n8k16.row.col.f32.bf16.bf16.f32 "
                    "{%0,%1,%2,%3}, {%4,%5,%6,%7}, {%8,%9}, {%0,%1,%2,%3};"
                    : "+f"(d[0]), "+f"(d[1]), "+f"(d[2]), "+f"(d[3])
                    : "r"(a[mf][0]), "r"(a[mf][1]), "r"(a[mf][2]), "r"(a[mf][3]), "r"(b2), "r"(b3));
            }
        }
        if (p == 1) {
            // restage B with lo plane
            __syncthreads();
            for (int idx = tid; idx < N * 16; idx += 512) {
                int r = idx >> 4, ch = idx & 15;
                uint4 v = *(const uint4*)(Blo + r * DD + ch * 8);
                *(uint4*)(smem + BOFF + r * 256 + ((ch ^ (r & 7)) << 4)) = v;
            }
            __syncthreads();
        }
    }

    // ---------- epilogue ----------
    int g = lane >> 2, tg = lane & 3;
#pragma unroll
    for (int mf = 0; mf < MF; mf++) {
        int r = row0 + wr * MF * 16 + mf * 16 + g;
        int c = wc * 16 + tg * 2;
#pragma unroll
        for (int n8 = 0; n8 < 2; n8++) {
            int cc = c + n8 * 8;
            float bx = bias[cc], by = bias[cc + 1];
            float* a0 = acc[mf * 2 + n8];
            if (r < NN)
                *(float2*)(Mout + (size_t)r * N + cc) = make_float2(a0[0] + bx, a0[1] + by);
            if (r + 8 < NN)
                *(float2*)(Mout + (size_t)(r + 8) * N + cc) = make_float2(a0[2] + bx, a0[3] + by);
        }
    }
}

// ---------------- head GEMM: fp32 X with inline split (N=128, M=128 tile) ----------------
__device__ __forceinline__ void stageA_x(char* smem, const float* __restrict__ X,
                                         int row0, int tid, int LO) {
    for (int idx = tid; idx < 2048; idx += 256) {
        int r = idx >> 4, ch = idx & 15, grow = row0 + r;
        __nv_bfloat16 o[8];
        if (grow < NN) {
            const float* p = X + (size_t)grow * DD + ch * 8;
            float4 v0 = *(const float4*)p, v1 = *(const float4*)(p + 4);
            float f[8] = {v0.x, v0.y, v0.z, v0.w, v1.x, v1.y, v1.z, v1.w};
#pragma unroll
            for (int j = 0; j < 8; j++) {
                __nv_bfloat16 h, l;
                split2(f[j], h, l);
                o[j] = LO ? l : h;
            }
        } else {
#pragma unroll
            for (int j = 0; j < 8; j++) o[j] = __float2bfloat16(0.f);
        }
        *(uint4*)(smem + r * 256 + ((ch ^ (r & 7)) << 4)) = *(uint4*)o;
    }
}
__device__ __forceinline__ void stageB128(char* smem, const __nv_bfloat16* __restrict__ B,
                                          int tid) {
    for (int idx = tid; idx < 128 * 16; idx += 256) {
        int r = idx >> 4, ch = idx & 15;
        uint4 v = *(const uint4*)(B + r * DD + ch * 8);
        *(uint4*)(smem + 32768 + r * 256 + ((ch ^ (r & 7)) << 4)) = v;
    }
}

__device__ __forceinline__ void mma_pass128(uint32_t sb, float (&acc)[16][4],
                                            int wid, int lane) {
    int wr = wid & 3, wc = wid >> 2, lr = lane & 7;
    int a_half = (lane >> 3) & 1, a_kc = lane >> 4;
    int b_kc = (lane >> 3) & 1, b_nh = lane >> 4;
#pragma unroll
    for (int ks = 0; ks < 8; ks++) {
        int c0 = ks * 2;
        uint32_t a[2][4];
#pragma unroll
        for (int mf = 0; mf < 2; mf++) {
            uint32_t addr = sb + (uint32_t)((wr * 32 + mf * 16 + a_half * 8 + lr) * 256)
                          + (uint32_t)(((c0 + a_kc) ^ lr) << 4);
            asm volatile("ldmatrix.sync.aligned.m8n8.x4.shared.b16 {%0,%1,%2,%3}, [%4];"
                : "=r"(a[mf][0]), "=r"(a[mf][1]), "=r"(a[mf][2]), "=r"(a[mf][3]) : "r"(addr));
        }
#pragma unroll
        for (int nf = 0; nf < 4; nf++) {
            uint32_t addr = sb + 32768u + (uint32_t)((wc * 64 + nf * 16 + b_nh * 8 + lr) * 256)
                          + (uint32_t)(((c0 + b_kc) ^ lr) << 4);
            uint32_t b0, b1, b2, b3;
            asm volatile("ldmatrix.sync.aligned.m8n8.x4.shared.b16 {%0,%1,%2,%3}, [%4];"
                : "=r"(b0), "=r"(b1), "=r"(b2), "=r"(b3) : "r"(addr));
#pragma unroll
            for (int mf = 0; mf < 2; mf++) {
                float* c = acc[mf * 8 + 2 * nf];
                asm volatile("mma.sync.aligned.m16n8k16.row.col.f32.bf16.bf16.f32 "
                    "{%0,%1,%2,%3}, {%4,%5,%6,%7}, {%8,%9}, {%0,%1,%2,%3};"
                    : "+f"(c[0]), "+f"(c[1]), "+f"(c[2]), "+f"(c[3])
                    : "r"(a[mf][0]), "r"(a[mf][1]), "r"(a[mf][2]), "r"(a[mf][3]), "r"(b0), "r"(b1));
                float* d = acc[mf * 8 + 2 * nf + 1];
                asm volatile("mma.sync.aligned.m16n8k16.row.col.f32.bf16.bf16.f32 "
                    "{%0,%1,%2,%3}, {%4,%5,%6,%7}, {%8,%9}, {%0,%1,%2,%3};"
                    : "+f"(d[0]), "+f"(d[1]), "+f"(d[2]), "+f"(d[3])
                    : "r"(a[mf][0]), "r"(a[mf][1]), "r"(a[mf][2]), "r"(a[mf][3]), "r"(b2), "r"(b3));
            }
        }
    }
}

__global__ void __launch_bounds__(256, 2) gemm_x(
    const float* __restrict__ X,
    const __nv_bfloat16* __restrict__ Bhi, const __nv_bfloat16* __restrict__ Blo,
    const float* __restrict__ bias, float* __restrict__ C)
{
    extern __shared__ char smem[];
    uint32_t sb = smem_u32(smem);
    int tid = threadIdx.x, wid = tid >> 5, lane = tid & 31;
    int row0 = blockIdx.x * 128;

    float acc[16][4];
#pragma unroll
    for (int i = 0; i < 16; i++)
#pragma unroll
        for (int j = 0; j < 4; j++) acc[i][j] = 0.f;

    stageA_x(smem, X, row0, tid, 0);
    stageB128(smem, Bhi, tid);
    __syncthreads();
    mma_pass128(sb, acc, wid, lane);
    __syncthreads();
    stageA_x(smem, X, row0, tid, 1);
    __syncthreads();
    mma_pass128(sb, acc, wid, lane);
    __syncthreads();
    stageA_x(smem, X, row0, tid, 0);
    stageB128(smem, Blo, tid);
    __syncthreads();
    mma_pass128(sb, acc, wid, lane);

    int wr = wid & 3, wc = wid >> 2;
    int g = lane >> 2, tg = lane & 3;
#pragma unroll
    for (int mf = 0; mf < 2; mf++) {
        int r = row0 + wr * 32 + mf * 16 + g;
#pragma unroll
        for (int n8 = 0; n8 < 8; n8++) {
            int c = wc * 64 + n8 * 8 + tg * 2;
            float bx = bias[c], by = bias[c + 1];
            float* a0 = acc[mf * 8 + n8];
            if (r < NN)
                *(float2*)(C + (size_t)r * 128 + c) = make_float2(a0[0] + bx, a0[1] + by);
            if (r + 8 < NN)
                *(float2*)(C + (size_t)(r + 8) * 128 + c) = make_float2(a0[2] + bx, a0[3] + by);
        }
    }
}

// ---------------- launch ----------------
extern "C" void kernel_launch(void* const* d_in, const int* in_sizes, int n_in,
                              void* d_out, int out_size) {
    const float* x    = (const float*)d_in[0];
    const void*  ei   = d_in[1];
    const float* W1   = (const float*)d_in[2];
    const float* b1   = (const float*)d_in[3];
    const float* W2   = (const float*)d_in[4];
    const float* b2   = (const float*)d_in[5];
    const float* Wout = (const float*)d_in[6];
    const float* bout = (const float*)d_in[7];
    float* out = (float*)d_out;

    float *mA, *mB;
    __nv_bfloat16 *w1h, *w1l, *w2h, *w2l, *woh, *wol;
    cudaGetSymbolAddress((void**)&mA, g_mA);
    cudaGetSymbolAddress((void**)&mB, g_mB);
    cudaGetSymbolAddress((void**)&w1h, g_w1h); cudaGetSymbolAddress((void**)&w1l, g_w1l);
    cudaGetSymbolAddress((void**)&w2h, g_w2h); cudaGetSymbolAddress((void**)&w2l, g_w2l);
    cudaGetSymbolAddress((void**)&woh, g_woh); cudaGetSymbolAddress((void**)&wol, g_wol);

    const int SMX    = 65536;                 // gemm_x: 32K A + 32K B
    const int SMF128 = 66048 + 128 * 256;     // 98816
    const int SMF64  = 66048 + 64 * 256;      // 82432
    static cudaStream_t s2 = nullptr;
    static cudaEvent_t evF = nullptr, evJ = nullptr;
    if (!s2) {
        cudaFuncSetAttribute(gemm_x, cudaFuncAttributeMaxDynamicSharedMemorySize, SMX);
        cudaFuncSetAttribute(pool_fused<128, 0>, cudaFuncAttributeMaxDynamicSharedMemorySize, SMF128);
        cudaFuncSetAttribute(pool_fused<128, 1>, cudaFuncAttributeMaxDynamicSharedMemorySize, SMF128);
        cudaFuncSetAttribute(pool_fused<64, 1>,  cudaFuncAttributeMaxDynamicSharedMemorySize, SMF64);
        cudaStreamCreateWithFlags(&s2, cudaStreamNonBlocking);
        cudaEventCreateWithFlags(&evF, cudaEventDisableTiming);
        cudaEventCreateWithFlags(&evJ, cudaEventDisableTiming);
    }

    // fork: CSR build on side stream
    cudaEventRecord(evF, 0);
    cudaStreamWaitEvent(s2, evF, 0);
    zero_detect_kernel<<<NB, 256, 0, s2>>>((const unsigned int*)ei);
    hist_kernel<<<(EE + 255) / 256, 256, 0, s2>>>(ei);
    partial_kernel<<<NB, 256, 0, s2>>>();
    scanpart_kernel<<<1, 256, 0, s2>>>();
    offs_kernel<<<NB, 256, 0, s2>>>();
    fill_kernel<<<(EE + 255) / 256, 256, 0, s2>>>(ei);
    cudaEventRecord(evJ, s2);

    // main stream: weights + head GEMM
    tw_all_kernel<<<(32768 + DOUT * DD + 255) / 256, 256>>>(W1, W2, Wout);

    const int gx = (NN + 127) / 128;   // 391
    const int gf = (NN + 63) / 64;     // 782

    gemm_x<<<gx, 256, SMX>>>(x, w1h, w1l, b1, mA);   // m1 = x@W1+b1

    cudaStreamWaitEvent(0, evJ, 0);    // CSR ready before first gather

    pool_fused<128, 0><<<gf, 512, SMF128>>>(mA, w1h, w1l, b1, mB);   // h1=A m1; m2=h1 W1+b1
    pool_fused<128, 1><<<gf, 512, SMF128>>>(mB, w2h, w2l, b2, mA);   // h2=A m2; m3=relu(h2) W2+b2
    pool_fused<128, 0><<<gf, 512, SMF128>>>(mA, w2h, w2l, b2, mB);   // h3=A m3; m4=h3 W2+b2
    pool_fused<64, 1><<<gf, 512, SMF64>>>(mB, woh, wol, bout, out);  // h4=A m4; out=relu(h4) Wout+bout
}

// round 8
// speedup vs baseline: 1.1586x; 1.1586x over previous
#include <cuda_runtime.h>
#include <cuda_bf16.h>
#include <cstdint>

#define NN   50000
#define EE   600000
#define DD   128
#define DOUT 64
#define NB   ((NN + 255) / 256)   // 196

// ---------------- scratch ----------------
__device__ float g_mA[(size_t)NN * DD];
__device__ float g_mB[(size_t)NN * DD];
__device__ __nv_bfloat16 g_w1h[DD * DD], g_w1l[DD * DD];      // W1^T split
__device__ __nv_bfloat16 g_w2h[DD * DD], g_w2l[DD * DD];      // (W2^2)^T split
__device__ __nv_bfloat16 g_woh[DOUT * DD], g_wol[DOUT * DD];  // Wout^T split
__device__ float g_bw1[DD], g_bw2[DD];                        // b1@W1, b2@W2
__device__ float g_degf[NN], g_adeg[NN];
__device__ int g_deg[NN], g_cnt[NN], g_off[NN + 1];
__device__ int g_part[NB], g_poff[NB];
__device__ int g_csr[EE];
__device__ int g_is64;

__device__ __forceinline__ uint32_t smem_u32(const void* p) {
    uint32_t a;
    asm("{ .reg .u64 t; cvta.to.shared.u64 t, %1; cvt.u32.u64 %0, t; }" : "=r"(a) : "l"(p));
    return a;
}

__device__ __forceinline__ int edge_idx(const void* ei, int which, int e) {
    if (g_is64) return (int)((const long long*)ei)[(size_t)which * EE + e];
    return ((const int*)ei)[which * EE + e];
}

// ---------------- CSR build (side stream) ----------------
__global__ void zero_detect_kernel(const unsigned int* __restrict__ w) {
    int i = blockIdx.x * blockDim.x + threadIdx.x;
    if (i < NN) { g_deg[i] = 0; g_cnt[i] = 0; }
    if (i == 0) {
        int is64 = 1;
        for (int j = 1; j < 128; j += 2)
            if (w[j] != 0u) { is64 = 0; break; }
        g_is64 = is64;
    }
}
__global__ void hist_kernel(const void* ei) {
    int e = blockIdx.x * blockDim.x + threadIdx.x;
    if (e < EE) atomicAdd(&g_deg[edge_idx(ei, 1, e)], 1);
}
__global__ void partial_kernel() {
    __shared__ int sh[256];
    int t = threadIdx.x, i = blockIdx.x * 256 + t;
    sh[t] = (i < NN) ? g_deg[i] : 0;
    __syncthreads();
    for (int d = 128; d > 0; d >>= 1) {
        if (t < d) sh[t] += sh[t + d];
        __syncthreads();
    }
    if (t == 0) g_part[blockIdx.x] = sh[0];
}
__global__ void scanpart_kernel() {
    __shared__ int sh[256];
    int t = threadIdx.x;
    int v = (t < NB) ? g_part[t] : 0;
    sh[t] = v;
    __syncthreads();
    for (int d = 1; d < 256; d <<= 1) {
        int u = (t >= d) ? sh[t - d] : 0;
        __syncthreads();
        sh[t] += u;
        __syncthreads();
    }
    if (t < NB) g_poff[t] = sh[t] - v;
    if (t == 0) g_off[NN] = EE;
}
__global__ void offs_kernel() {
    __shared__ int sh[256];
    int t = threadIdx.x, i = blockIdx.x * 256 + t;
    int v = (i < NN) ? g_deg[i] : 0;
    sh[t] = v;
    __syncthreads();
    for (int d = 1; d < 256; d <<= 1) {
        int u = (t >= d) ? sh[t - d] : 0;
        __syncthreads();
        sh[t] += u;
        __syncthreads();
    }
    if (i < NN) g_off[i] = g_poff[blockIdx.x] + sh[t] - v;
}
__global__ void fill_kernel(const void* ei) {
    int e = blockIdx.x * blockDim.x + threadIdx.x;
    if (e < EE) {
        int d = edge_idx(ei, 1, e);
        int s = edge_idx(ei, 0, e);
        g_csr[g_off[d] + atomicAdd(&g_cnt[d], 1)] = s;
    }
}
// deg (float) and A·deg per node; needs g_deg (hist) + g_csr (fill)
__global__ void adeg_kernel() {
    int i = blockIdx.x * blockDim.x + threadIdx.x;
    if (i >= NN) return;
    int b = g_off[i], e = g_off[i + 1];
    float s = 0.f;
    for (int k = b; k < e; k++) s += (float)g_deg[g_csr[k]];
    g_adeg[i] = s;
    g_degf[i] = (float)(e - b);
}

// ---------------- split helper ----------------
__device__ __forceinline__ void split2(float x, __nv_bfloat16& h, __nv_bfloat16& l) {
    h = __float2bfloat16(x);
    l = __float2bfloat16(x - __bfloat162float(h));
}

// ---------------- one prep kernel: W1^T split, (W2^2)^T split, Wout^T split, bW vectors ----
__global__ void prep_all_kernel(const float* __restrict__ W1, const float* __restrict__ W2,
                                const float* __restrict__ Wo, const float* __restrict__ b1,
                                const float* __restrict__ b2) {
    int i = blockIdx.x * blockDim.x + threadIdx.x;
    if (i < 16384) {                       // W1^T
        int n = i >> 7, k = i & 127;
        split2(W1[k * DD + n], g_w1h[i], g_w1l[i]);
    } else if (i < 32768) {                // (W2·W2)^T : S[k,n] stored at [n*128+k]
        int j = i - 16384;
        int n = j >> 7, k = j & 127;
        float s = 0.f;
        for (int t = 0; t < DD; t++) s += W2[k * DD + t] * W2[t * DD + n];
        split2(s, g_w2h[j], g_w2l[j]);
    } else if (i < 32768 + DOUT * DD) {    // Wout^T
        int j = i - 32768;
        int n = j >> 7, k = j & 127;
        split2(Wo[k * DOUT + n], g_woh[j], g_wol[j]);
    } else if (i < 32768 + DOUT * DD + 2 * DD) {   // bw vectors
        int c = i - (32768 + DOUT * DD);
        if (c < DD) {
            float s = 0.f;
            for (int k = 0; k < DD; k++) s += b1[k] * W1[k * DD + c];
            g_bw1[c] = s;
        } else {
            c -= DD;
            float s = 0.f;
            for (int k = 0; k < DD; k++) s += b2[k] * W2[k * DD + c];
            g_bw2[c] = s;
        }
    }
}

// ---------------- GEMM: fp32 A inline-split, 3-pass split-bf16 HMMA ----------------
// smem: AHI [0,32K), ALO [32K,64K), B [64K, 64K+N*256)
// EPI: 0 = none; 1 = rowbias (adeg*bw + deg*b) + relu; 2 = vector bias
template <int N>
__device__ __forceinline__ void stageB(char* smem, const __nv_bfloat16* __restrict__ B, int tid) {
    for (int idx = tid; idx < N * 16; idx += 256) {
        int r = idx >> 4, ch = idx & 15;
        uint4 v = *(const uint4*)(B + r * DD + ch * 8);
        *(uint4*)(smem + 65536 + r * 256 + ((ch ^ (r & 7)) << 4)) = v;
    }
}

template <int N>
__device__ __forceinline__ void mma_pass(uint32_t sb, uint32_t aoff, float (&acc)[N / 8][4],
                                         int wid, int lane) {
    constexpr int NW = N / 2, NF16 = NW / 16, NF8 = NW / 8;
    int wr = wid & 3, wc = wid >> 2, lr = lane & 7;
    int a_half = (lane >> 3) & 1, a_kc = lane >> 4;
    int b_kc = (lane >> 3) & 1, b_nh = lane >> 4;
#pragma unroll
    for (int ks = 0; ks < 8; ks++) {
        int c0 = ks * 2;
        uint32_t a[2][4];
#pragma unroll
        for (int mf = 0; mf < 2; mf++) {
            uint32_t addr = sb + aoff + (uint32_t)((wr * 32 + mf * 16 + a_half * 8 + lr) * 256)
                          + (uint32_t)(((c0 + a_kc) ^ lr) << 4);
            asm volatile("ldmatrix.sync.aligned.m8n8.x4.shared.b16 {%0,%1,%2,%3}, [%4];"
                : "=r"(a[mf][0]), "=r"(a[mf][1]), "=r"(a[mf][2]), "=r"(a[mf][3]) : "r"(addr));
        }
#pragma unroll
        for (int nf = 0; nf < NF16; nf++) {
            uint32_t addr = sb + 65536u + (uint32_t)((wc * NW + nf * 16 + b_nh * 8 + lr) * 256)
                          + (uint32_t)(((c0 + b_kc) ^ lr) << 4);
            uint32_t b0, b1r, b2r, b3;
            asm volatile("ldmatrix.sync.aligned.m8n8.x4.shared.b16 {%0,%1,%2,%3}, [%4];"
                : "=r"(b0), "=r"(b1r), "=r"(b2r), "=r"(b3) : "r"(addr));
#pragma unroll
            for (int mf = 0; mf < 2; mf++) {
                float* c = acc[mf * NF8 + 2 * nf];
                asm volatile("mma.sync.aligned.m16n8k16.row.col.f32.bf16.bf16.f32 "
                    "{%0,%1,%2,%3}, {%4,%5,%6,%7}, {%8,%9}, {%0,%1,%2,%3};"
                    : "+f"(c[0]), "+f"(c[1]), "+f"(c[2]), "+f"(c[3])
                    : "r"(a[mf][0]), "r"(a[mf][1]), "r"(a[mf][2]), "r"(a[mf][3]), "r"(b0), "r"(b1r));
                float* d = acc[mf * NF8 + 2 * nf + 1];
                asm volatile("mma.sync.aligned.m16n8k16.row.col.f32.bf16.bf16.f32 "
                    "{%0,%1,%2,%3}, {%4,%5,%6,%7}, {%8,%9}, {%0,%1,%2,%3};"
                    : "+f"(d[0]), "+f"(d[1]), "+f"(d[2]), "+f"(d[3])
                    : "r"(a[mf][0]), "r"(a[mf][1]), "r"(a[mf][2]), "r"(a[mf][3]), "r"(b2r), "r"(b3));
            }
        }
    }
}

template <int N, int EPI>
__global__ void __launch_bounds__(256, 2) gemm_f32(
    const float* __restrict__ A,
    const __nv_bfloat16* __restrict__ Bhi, const __nv_bfloat16* __restrict__ Blo,
    const float* __restrict__ bias, const float* __restrict__ bw,
    float* __restrict__ C)
{
    extern __shared__ char smem[];
    uint32_t sb = smem_u32(smem);
    int tid = threadIdx.x, wid = tid >> 5, lane = tid & 31;
    int row0 = blockIdx.x * 128;

    // stage A hi+lo once (inline split from fp32)
    for (int idx = tid; idx < 2048; idx += 256) {
        int r = idx >> 4, ch = idx & 15, grow = row0 + r;
        __nv_bfloat16 h[8], l[8];
        if (grow < NN) {
            const float* p = A + (size_t)grow * DD + ch * 8;
            float4 v0 = *(const float4*)p, v1 = *(const float4*)(p + 4);
            float f[8] = {v0.x, v0.y, v0.z, v0.w, v1.x, v1.y, v1.z, v1.w};
#pragma unroll
            for (int j = 0; j < 8; j++) split2(f[j], h[j], l[j]);
        } else {
#pragma unroll
            for (int j = 0; j < 8; j++) { h[j] = __float2bfloat16(0.f); l[j] = h[j]; }
        }
        int off = r * 256 + ((ch ^ (r & 7)) << 4);
        *(uint4*)(smem + off) = *(uint4*)h;
        *(uint4*)(smem + 32768 + off) = *(uint4*)l;
    }
    stageB<N>(smem, Bhi, tid);
    __syncthreads();

    float acc[N / 8][4];
#pragma unroll
    for (int i = 0; i < N / 8; i++)
#pragma unroll
        for (int j = 0; j < 4; j++) acc[i][j] = 0.f;

    mma_pass<N>(sb, 0u, acc, wid, lane);        // Ahi * Bhi
    mma_pass<N>(sb, 32768u, acc, wid, lane);    // Alo * Bhi
    __syncthreads();
    stageB<N>(smem, Blo, tid);
    __syncthreads();
    mma_pass<N>(sb, 0u, acc, wid, lane);        // Ahi * Blo

    // epilogue
    constexpr int NW = N / 2, NF8 = NW / 8;
    int wr = wid & 3, wc = wid >> 2;
    int g = lane >> 2, tg = lane & 3;
#pragma unroll
    for (int mf = 0; mf < 2; mf++) {
        int r = row0 + wr * 32 + mf * 16 + g;
        float d0 = 0.f, a0 = 0.f, d1 = 0.f, a1 = 0.f;
        if (EPI == 1) {
            if (r < NN)     { d0 = g_degf[r];     a0 = g_adeg[r]; }
            if (r + 8 < NN) { d1 = g_degf[r + 8]; a1 = g_adeg[r + 8]; }
        }
#pragma unroll
        for (int n8 = 0; n8 < NF8; n8++) {
            int c = wc * NW + n8 * 8 + tg * 2;
            float* v = acc[mf * NF8 + n8];
            float o0x = v[0], o0y = v[1], o1x = v[2], o1y = v[3];
            if (EPI == 1) {
                float bwx = bw[c], bwy = bw[c + 1], bx = bias[c], by = bias[c + 1];
                o0x = fmaxf(o0x + a0 * bwx + d0 * bx, 0.f);
                o0y = fmaxf(o0y + a0 * bwy + d0 * by, 0.f);
                o1x = fmaxf(o1x + a1 * bwx + d1 * bx, 0.f);
                o1y = fmaxf(o1y + a1 * bwy + d1 * by, 0.f);
            } else if (EPI == 2) {
                float bx = bias[c], by = bias[c + 1];
                o0x += bx; o0y += by; o1x += bx; o1y += by;
            }
            if (r < NN)
                *(float2*)(C + (size_t)r * N + c) = make_float2(o0x, o0y);
            if (r + 8 < NN)
                *(float2*)(C + (size_t)(r + 8) * N + c) = make_float2(o1x, o1y);
        }
    }
}

// ---------------- gather-sum (warp per node, fp32 -> fp32) ----------------
__global__ void gather_kernel(const float* __restrict__ m, float* __restrict__ o) {
    int gw = (blockIdx.x * blockDim.x + threadIdx.x) >> 5;
    int lane = threadIdx.x & 31;
    if (gw >= NN) return;
    int beg = g_off[gw], end = g_off[gw + 1];
    const float4* base = (const float4*)m;
    float4 acc = make_float4(0.f, 0.f, 0.f, 0.f);
    int e = beg;
    for (; e + 4 <= end; e += 4) {
        int s0 = g_csr[e], s1 = g_csr[e + 1], s2 = g_csr[e + 2], s3 = g_csr[e + 3];
        float4 v0 = base[s0 * 32 + lane];
        float4 v1 = base[s1 * 32 + lane];
        float4 v2 = base[s2 * 32 + lane];
        float4 v3 = base[s3 * 32 + lane];
        acc.x += (v0.x + v1.x) + (v2.x + v3.x);
        acc.y += (v0.y + v1.y) + (v2.y + v3.y);
        acc.z += (v0.z + v1.z) + (v2.z + v3.z);
        acc.w += (v0.w + v1.w) + (v2.w + v3.w);
    }
    for (; e < end; e++) {
        float4 v = base[g_csr[e] * 32 + lane];
        acc.x += v.x; acc.y += v.y; acc.z += v.z; acc.w += v.w;
    }
    ((float4*)o)[gw * 32 + lane] = acc;
}

// ---------------- launch ----------------
extern "C" void kernel_launch(void* const* d_in, const int* in_sizes, int n_in,
                              void* d_out, int out_size) {
    const float* x    = (const float*)d_in[0];
    const void*  ei   = d_in[1];
    const float* W1   = (const float*)d_in[2];
    const float* b1   = (const float*)d_in[3];
    const float* W2   = (const float*)d_in[4];
    const float* b2   = (const float*)d_in[5];
    const float* Wout = (const float*)d_in[6];
    const float* bout = (const float*)d_in[7];
    float* out = (float*)d_out;

    float *mA, *mB, *bw1, *bw2;
    __nv_bfloat16 *w1h, *w1l, *w2h, *w2l, *woh, *wol;
    cudaGetSymbolAddress((void**)&mA, g_mA);
    cudaGetSymbolAddress((void**)&mB, g_mB);
    cudaGetSymbolAddress((void**)&w1h, g_w1h); cudaGetSymbolAddress((void**)&w1l, g_w1l);
    cudaGetSymbolAddress((void**)&w2h, g_w2h); cudaGetSymbolAddress((void**)&w2l, g_w2l);
    cudaGetSymbolAddress((void**)&woh, g_woh); cudaGetSymbolAddress((void**)&wol, g_wol);
    cudaGetSymbolAddress((void**)&bw1, g_bw1); cudaGetSymbolAddress((void**)&bw2, g_bw2);

    const int SM128 = 65536 + 128 * 256;   // 98304
    const int SM64  = 65536 + 64 * 256;    // 81920
    static cudaStream_t s2 = nullptr;
    static cudaEvent_t evF = nullptr, evJ = nullptr;
    if (!s2) {
        cudaFuncSetAttribute(gemm_f32<128, 0>, cudaFuncAttributeMaxDynamicSharedMemorySize, SM128);
        cudaFuncSetAttribute(gemm_f32<128, 1>, cudaFuncAttributeMaxDynamicSharedMemorySize, SM128);
        cudaFuncSetAttribute(gemm_f32<64, 2>,  cudaFuncAttributeMaxDynamicSharedMemorySize, SM64);
        cudaStreamCreateWithFlags(&s2, cudaStreamNonBlocking);
        cudaEventCreateWithFlags(&evF, cudaEventDisableTiming);
        cudaEventCreateWithFlags(&evJ, cudaEventDisableTiming);
    }

    // fork: CSR build + deg/adeg on side stream
    cudaEventRecord(evF, 0);
    cudaStreamWaitEvent(s2, evF, 0);
    zero_detect_kernel<<<NB, 256, 0, s2>>>((const unsigned int*)ei);
    hist_kernel<<<(EE + 255) / 256, 256, 0, s2>>>(ei);
    partial_kernel<<<NB, 256, 0, s2>>>();
    scanpart_kernel<<<1, 256, 0, s2>>>();
    offs_kernel<<<NB, 256, 0, s2>>>();
    fill_kernel<<<(EE + 255) / 256, 256, 0, s2>>>(ei);
    adeg_kernel<<<NB, 256, 0, s2>>>();
    cudaEventRecord(evJ, s2);

    // main stream: prep (W1t, W2sq_t, Wout_t, bw vectors) + GEMM1 (CSR-independent)
    const int PREP = 32768 + DOUT * DD + 2 * DD;
    prep_all_kernel<<<(PREP + 255) / 256, 256>>>(W1, W2, Wout, b1, b2);

    const int gx = (NN + 127) / 128;        // 391
    const int gg = (NN * 32 + 255) / 256;   // 6250

    gemm_f32<128, 0><<<gx, 256, SM128>>>(x, w1h, w1l, nullptr, nullptr, mA);  // mA = x@W1

    cudaStreamWaitEvent(0, evJ, 0);   // join: CSR + deg/adeg ready

    // layer 1: x2 = A^2(xW1)W1 + adeg⊗(b1W1) + deg⊗b1, then relu
    gather_kernel<<<gg, 256>>>(mA, mB);                                        // mB = A mA
    gather_kernel<<<gg, 256>>>(mB, mA);                                        // mA = A^2 (xW1)
    gemm_f32<128, 1><<<gx, 256, SM128>>>(mA, w1h, w1l, b1, bw1, mB);           // mB = relu(...)
    // layer 2: y = A^2(h)W2^2 + adeg⊗(b2W2) + deg⊗b2, then relu
    gather_kernel<<<gg, 256>>>(mB, mA);                                        // mA = A h
    gather_kernel<<<gg, 256>>>(mA, mB);                                        // mB = A^2 h
    gemm_f32<128, 1><<<gx, 256, SM128>>>(mB, w2h, w2l, b2, bw2, mA);           // mA = relu(...)
    // output projection
    gemm_f32<64, 2><<<gx, 256, SM64>>>(mA, woh, wol, bout, nullptr, out);
}

// round 9
// speedup vs baseline: 1.2801x; 1.1049x over previous
#include <cuda_runtime.h>
#include <cuda_bf16.h>
#include <cuda_fp16.h>
#include <cstdint>

#define NN   50000
#define EE   600000
#define DD   128
#define DOUT 64
#define NB   ((NN + 255) / 256)   // 196

// ---------------- scratch ----------------
__device__ __half g_h1[(size_t)NN * DD];   // fp16 messages (gather input)
__device__ __half g_h2[(size_t)NN * DD];   // fp16 gather-chain intermediate
__device__ float  g_mF[(size_t)NN * DD];   // fp32 gather output -> gemm A
__device__ float  g_mG[(size_t)NN * DD];   // fp32 layer-2 features
__device__ __nv_bfloat16 g_w1h[DD * DD], g_w1l[DD * DD];      // W1^T split
__device__ __nv_bfloat16 g_w2h[DD * DD], g_w2l[DD * DD];      // (W2^2)^T split
__device__ __nv_bfloat16 g_woh[DOUT * DD], g_wol[DOUT * DD];  // Wout^T split
__device__ float g_bw1[DD], g_bw2[DD];                        // b1@W1, b2@W2
__device__ float g_degf[NN], g_adeg[NN];
__device__ int g_deg[NN], g_cnt[NN], g_off[NN + 1];
__device__ int g_part[NB], g_poff[NB];
__device__ int g_csr[EE];
__device__ int g_is64;

__device__ __forceinline__ uint32_t smem_u32(const void* p) {
    uint32_t a;
    asm("{ .reg .u64 t; cvta.to.shared.u64 t, %1; cvt.u32.u64 %0, t; }" : "=r"(a) : "l"(p));
    return a;
}

__device__ __forceinline__ int edge_idx(const void* ei, int which, int e) {
    if (g_is64) return (int)((const long long*)ei)[(size_t)which * EE + e];
    return ((const int*)ei)[which * EE + e];
}

// ---------------- CSR build (side stream) ----------------
__global__ void zero_detect_kernel(const unsigned int* __restrict__ w) {
    int i = blockIdx.x * blockDim.x + threadIdx.x;
    if (i < NN) { g_deg[i] = 0; g_cnt[i] = 0; }
    if (i == 0) {
        int is64 = 1;
        for (int j = 1; j < 128; j += 2)
            if (w[j] != 0u) { is64 = 0; break; }
        g_is64 = is64;
    }
}
__global__ void hist_kernel(const void* ei) {
    int e = blockIdx.x * blockDim.x + threadIdx.x;
    if (e < EE) atomicAdd(&g_deg[edge_idx(ei, 1, e)], 1);
}
__global__ void partial_kernel() {
    __shared__ int sh[256];
    int t = threadIdx.x, i = blockIdx.x * 256 + t;
    sh[t] = (i < NN) ? g_deg[i] : 0;
    __syncthreads();
    for (int d = 128; d > 0; d >>= 1) {
        if (t < d) sh[t] += sh[t + d];
        __syncthreads();
    }
    if (t == 0) g_part[blockIdx.x] = sh[0];
}
__global__ void scanpart_kernel() {
    __shared__ int sh[256];
    int t = threadIdx.x;
    int v = (t < NB) ? g_part[t] : 0;
    sh[t] = v;
    __syncthreads();
    for (int d = 1; d < 256; d <<= 1) {
        int u = (t >= d) ? sh[t - d] : 0;
        __syncthreads();
        sh[t] += u;
        __syncthreads();
    }
    if (t < NB) g_poff[t] = sh[t] - v;
    if (t == 0) g_off[NN] = EE;
}
__global__ void offs_kernel() {
    __shared__ int sh[256];
    int t = threadIdx.x, i = blockIdx.x * 256 + t;
    int v = (i < NN) ? g_deg[i] : 0;
    sh[t] = v;
    __syncthreads();
    for (int d = 1; d < 256; d <<= 1) {
        int u = (t >= d) ? sh[t - d] : 0;
        __syncthreads();
        sh[t] += u;
        __syncthreads();
    }
    if (i < NN) g_off[i] = g_poff[blockIdx.x] + sh[t] - v;
}
__global__ void fill_kernel(const void* ei) {
    int e = blockIdx.x * blockDim.x + threadIdx.x;
    if (e < EE) {
        int d = edge_idx(ei, 1, e);
        int s = edge_idx(ei, 0, e);
        g_csr[g_off[d] + atomicAdd(&g_cnt[d], 1)] = s;
    }
}
__global__ void adeg_kernel() {
    int i = blockIdx.x * blockDim.x + threadIdx.x;
    if (i >= NN) return;
    int b = g_off[i], e = g_off[i + 1];
    float s = 0.f;
    for (int k = b; k < e; k++) s += (float)g_deg[g_csr[k]];
    g_adeg[i] = s;
    g_degf[i] = (float)(e - b);
}

// ---------------- split helper ----------------
__device__ __forceinline__ void split2(float x, __nv_bfloat16& h, __nv_bfloat16& l) {
    h = __float2bfloat16(x);
    l = __float2bfloat16(x - __bfloat162float(h));
}

// ---------------- prep: W1^T split, (W2^2)^T split, Wout^T split, bW vectors ----------------
__global__ void prep_all_kernel(const float* __restrict__ W1, const float* __restrict__ W2,
                                const float* __restrict__ Wo, const float* __restrict__ b1,
                                const float* __restrict__ b2) {
    int i = blockIdx.x * blockDim.x + threadIdx.x;
    if (i < 16384) {                       // W1^T
        int n = i >> 7, k = i & 127;
        split2(W1[k * DD + n], g_w1h[i], g_w1l[i]);
    } else if (i < 32768) {                // (W2*W2)^T
        int j = i - 16384;
        int n = j >> 7, k = j & 127;
        float s = 0.f;
        for (int t = 0; t < DD; t++) s += W2[k * DD + t] * W2[t * DD + n];
        split2(s, g_w2h[j], g_w2l[j]);
    } else if (i < 32768 + DOUT * DD) {    // Wout^T
        int j = i - 32768;
        int n = j >> 7, k = j & 127;
        split2(Wo[k * DOUT + n], g_woh[j], g_wol[j]);
    } else if (i < 32768 + DOUT * DD + 2 * DD) {
        int c = i - (32768 + DOUT * DD);
        if (c < DD) {
            float s = 0.f;
            for (int k = 0; k < DD; k++) s += b1[k] * W1[k * DD + c];
            g_bw1[c] = s;
        } else {
            c -= DD;
            float s = 0.f;
            for (int k = 0; k < DD; k++) s += b2[k] * W2[k * DD + c];
            g_bw2[c] = s;
        }
    }
}

// ---------------- GEMM: fp32 A inline-split, 3-pass split-bf16 HMMA ----------------
// EPI: 0 = none; 1 = rowbias (adeg*bw + deg*b) + relu; 2 = vector bias
// OUTF: 0 -> fp16 output, 1 -> fp32 output
template <int N>
__device__ __forceinline__ void stageB(char* smem, const __nv_bfloat16* __restrict__ B, int tid) {
    for (int idx = tid; idx < N * 16; idx += 256) {
        int r = idx >> 4, ch = idx & 15;
        uint4 v = *(const uint4*)(B + r * DD + ch * 8);
        *(uint4*)(smem + 65536 + r * 256 + ((ch ^ (r & 7)) << 4)) = v;
    }
}

template <int N>
__device__ __forceinline__ void mma_pass(uint32_t sb, uint32_t aoff, float (&acc)[N / 8][4],
                                         int wid, int lane) {
    constexpr int NW = N / 2, NF16 = NW / 16, NF8 = NW / 8;
    int wr = wid & 3, wc = wid >> 2, lr = lane & 7;
    int a_half = (lane >> 3) & 1, a_kc = lane >> 4;
    int b_kc = (lane >> 3) & 1, b_nh = lane >> 4;
#pragma unroll
    for (int ks = 0; ks < 8; ks++) {
        int c0 = ks * 2;
        uint32_t a[2][4];
#pragma unroll
        for (int mf = 0; mf < 2; mf++) {
            uint32_t addr = sb + aoff + (uint32_t)((wr * 32 + mf * 16 + a_half * 8 + lr) * 256)
                          + (uint32_t)(((c0 + a_kc) ^ lr) << 4);
            asm volatile("ldmatrix.sync.aligned.m8n8.x4.shared.b16 {%0,%1,%2,%3}, [%4];"
                : "=r"(a[mf][0]), "=r"(a[mf][1]), "=r"(a[mf][2]), "=r"(a[mf][3]) : "r"(addr));
        }
#pragma unroll
        for (int nf = 0; nf < NF16; nf++) {
            uint32_t addr = sb + 65536u + (uint32_t)((wc * NW + nf * 16 + b_nh * 8 + lr) * 256)
                          + (uint32_t)(((c0 + b_kc) ^ lr) << 4);
            uint32_t b0, b1r, b2r, b3;
            asm volatile("ldmatrix.sync.aligned.m8n8.x4.shared.b16 {%0,%1,%2,%3}, [%4];"
                : "=r"(b0), "=r"(b1r), "=r"(b2r), "=r"(b3) : "r"(addr));
#pragma unroll
            for (int mf = 0; mf < 2; mf++) {
                float* c = acc[mf * NF8 + 2 * nf];
                asm volatile("mma.sync.aligned.m16n8k16.row.col.f32.bf16.bf16.f32 "
                    "{%0,%1,%2,%3}, {%4,%5,%6,%7}, {%8,%9}, {%0,%1,%2,%3};"
                    : "+f"(c[0]), "+f"(c[1]), "+f"(c[2]), "+f"(c[3])
                    : "r"(a[mf][0]), "r"(a[mf][1]), "r"(a[mf][2]), "r"(a[mf][3]), "r"(b0), "r"(b1r));
                float* d = acc[mf * NF8 + 2 * nf + 1];
                asm volatile("mma.sync.aligned.m16n8k16.row.col.f32.bf16.bf16.f32 "
                    "{%0,%1,%2,%3}, {%4,%5,%6,%7}, {%8,%9}, {%0,%1,%2,%3};"
                    : "+f"(d[0]), "+f"(d[1]), "+f"(d[2]), "+f"(d[3])
                    : "r"(a[mf][0]), "r"(a[mf][1]), "r"(a[mf][2]), "r"(a[mf][3]), "r"(b2r), "r"(b3));
            }
        }
    }
}

template <int N, int EPI, int OUTF>
__global__ void __launch_bounds__(256, 2) gemm_k(
    const float* __restrict__ A,
    const __nv_bfloat16* __restrict__ Bhi, const __nv_bfloat16* __restrict__ Blo,
    const float* __restrict__ bias, const float* __restrict__ bw,
    void* __restrict__ Cv)
{
    extern __shared__ char smem[];
    uint32_t sb = smem_u32(smem);
    int tid = threadIdx.x, wid = tid >> 5, lane = tid & 31;
    int row0 = blockIdx.x * 128;

    // stage A hi+lo (inline split from fp32)
    for (int idx = tid; idx < 2048; idx += 256) {
        int r = idx >> 4, ch = idx & 15, grow = row0 + r;
        __nv_bfloat16 h[8], l[8];
        if (grow < NN) {
            const float* p = A + (size_t)grow * DD + ch * 8;
            float4 v0 = *(const float4*)p, v1 = *(const float4*)(p + 4);
            float f[8] = {v0.x, v0.y, v0.z, v0.w, v1.x, v1.y, v1.z, v1.w};
#pragma unroll
            for (int j = 0; j < 8; j++) split2(f[j], h[j], l[j]);
        } else {
#pragma unroll
            for (int j = 0; j < 8; j++) { h[j] = __float2bfloat16(0.f); l[j] = h[j]; }
        }
        int off = r * 256 + ((ch ^ (r & 7)) << 4);
        *(uint4*)(smem + off) = *(uint4*)h;
        *(uint4*)(smem + 32768 + off) = *(uint4*)l;
    }
    stageB<N>(smem, Bhi, tid);
    __syncthreads();

    float acc[N / 8][4];
#pragma unroll
    for (int i = 0; i < N / 8; i++)
#pragma unroll
        for (int j = 0; j < 4; j++) acc[i][j] = 0.f;

    mma_pass<N>(sb, 0u, acc, wid, lane);        // Ahi * Bhi
    mma_pass<N>(sb, 32768u, acc, wid, lane);    // Alo * Bhi
    __syncthreads();
    stageB<N>(smem, Blo, tid);
    __syncthreads();
    mma_pass<N>(sb, 0u, acc, wid, lane);        // Ahi * Blo

    // epilogue
    constexpr int NW = N / 2, NF8 = NW / 8;
    int wr = wid & 3, wc = wid >> 2;
    int g = lane >> 2, tg = lane & 3;
#pragma unroll
    for (int mf = 0; mf < 2; mf++) {
        int r = row0 + wr * 32 + mf * 16 + g;
        float d0 = 0.f, a0 = 0.f, d1 = 0.f, a1 = 0.f;
        if (EPI == 1) {
            if (r < NN)     { d0 = g_degf[r];     a0 = g_adeg[r]; }
            if (r + 8 < NN) { d1 = g_degf[r + 8]; a1 = g_adeg[r + 8]; }
        }
#pragma unroll
        for (int n8 = 0; n8 < NF8; n8++) {
            int c = wc * NW + n8 * 8 + tg * 2;
            float* v = acc[mf * NF8 + n8];
            float o0x = v[0], o0y = v[1], o1x = v[2], o1y = v[3];
            if (EPI == 1) {
                float bwx = bw[c], bwy = bw[c + 1], bx = bias[c], by = bias[c + 1];
                o0x = fmaxf(o0x + a0 * bwx + d0 * bx, 0.f);
                o0y = fmaxf(o0y + a0 * bwy + d0 * by, 0.f);
                o1x = fmaxf(o1x + a1 * bwx + d1 * bx, 0.f);
                o1y = fmaxf(o1y + a1 * bwy + d1 * by, 0.f);
            } else if (EPI == 2) {
                float bx = bias[c], by = bias[c + 1];
                o0x += bx; o0y += by; o1x += bx; o1y += by;
            }
            if (OUTF) {
                float* C = (float*)Cv;
                if (r < NN)
                    *(float2*)(C + (size_t)r * N + c) = make_float2(o0x, o0y);
                if (r + 8 < NN)
                    *(float2*)(C + (size_t)(r + 8) * N + c) = make_float2(o1x, o1y);
            } else {
                __half* C = (__half*)Cv;
                if (r < NN)
                    *(__half2*)(C + (size_t)r * N + c) = __floats2half2_rn(o0x, o0y);
                if (r + 8 < NN)
                    *(__half2*)(C + (size_t)(r + 8) * N + c) = __floats2half2_rn(o1x, o1y);
            }
        }
    }
}

// ---------------- gather-sum (warp per node, fp16 in, fp16/fp32 out) ----------------
template <int OUTF>
__global__ void gather_kernel(const __half* __restrict__ m, void* __restrict__ o) {
    int gw = (blockIdx.x * blockDim.x + threadIdx.x) >> 5;
    int lane = threadIdx.x & 31;
    if (gw >= NN) return;
    int beg = g_off[gw], end = g_off[gw + 1];
    const uint2* base = (const uint2*)m;   // row = 32 x uint2 (256 B)
    float ax = 0.f, ay = 0.f, az = 0.f, aw = 0.f;
    int e = beg;
    for (; e + 8 <= end; e += 8) {
        int s[8];
#pragma unroll
        for (int i = 0; i < 8; i++) s[i] = g_csr[e + i];
        uint2 v[8];
#pragma unroll
        for (int i = 0; i < 8; i++) v[i] = base[s[i] * 32 + lane];
#pragma unroll
        for (int i = 0; i < 8; i++) {
            float2 f0 = __half22float2(*(__half2*)&v[i].x);
            float2 f1 = __half22float2(*(__half2*)&v[i].y);
            ax += f0.x; ay += f0.y; az += f1.x; aw += f1.y;
        }
    }
    for (; e < end; e++) {
        uint2 v = base[g_csr[e] * 32 + lane];
        float2 f0 = __half22float2(*(__half2*)&v.x);
        float2 f1 = __half22float2(*(__half2*)&v.y);
        ax += f0.x; ay += f0.y; az += f1.x; aw += f1.y;
    }
    if (OUTF) {
        ((float4*)o)[gw * 32 + lane] = make_float4(ax, ay, az, aw);
    } else {
        uint2 r;
        *(__half2*)&r.x = __floats2half2_rn(ax, ay);
        *(__half2*)&r.y = __floats2half2_rn(az, aw);
        ((uint2*)o)[gw * 32 + lane] = r;
    }
}

// ---------------- launch ----------------
extern "C" void kernel_launch(void* const* d_in, const int* in_sizes, int n_in,
                              void* d_out, int out_size) {
    const float* x    = (const float*)d_in[0];
    const void*  ei   = d_in[1];
    const float* W1   = (const float*)d_in[2];
    const float* b1   = (const float*)d_in[3];
    const float* W2   = (const float*)d_in[4];
    const float* b2   = (const float*)d_in[5];
    const float* Wout = (const float*)d_in[6];
    const float* bout = (const float*)d_in[7];
    float* out = (float*)d_out;

    __half *h1, *h2;
    float *mF, *mG, *bw1, *bw2;
    __nv_bfloat16 *w1h, *w1l, *w2h, *w2l, *woh, *wol;
    cudaGetSymbolAddress((void**)&h1, g_h1);
    cudaGetSymbolAddress((void**)&h2, g_h2);
    cudaGetSymbolAddress((void**)&mF, g_mF);
    cudaGetSymbolAddress((void**)&mG, g_mG);
    cudaGetSymbolAddress((void**)&w1h, g_w1h); cudaGetSymbolAddress((void**)&w1l, g_w1l);
    cudaGetSymbolAddress((void**)&w2h, g_w2h); cudaGetSymbolAddress((void**)&w2l, g_w2l);
    cudaGetSymbolAddress((void**)&woh, g_woh); cudaGetSymbolAddress((void**)&wol, g_wol);
    cudaGetSymbolAddress((void**)&bw1, g_bw1); cudaGetSymbolAddress((void**)&bw2, g_bw2);

    const int SM128 = 65536 + 128 * 256;   // 98304
    const int SM64  = 65536 + 64 * 256;    // 81920
    static cudaStream_t s2 = nullptr;
    static cudaEvent_t evF = nullptr, evJ = nullptr;
    if (!s2) {
        cudaFuncSetAttribute(gemm_k<128, 0, 0>, cudaFuncAttributeMaxDynamicSharedMemorySize, SM128);
        cudaFuncSetAttribute(gemm_k<128, 1, 0>, cudaFuncAttributeMaxDynamicSharedMemorySize, SM128);
        cudaFuncSetAttribute(gemm_k<128, 1, 1>, cudaFuncAttributeMaxDynamicSharedMemorySize, SM128);
        cudaFuncSetAttribute(gemm_k<64, 2, 1>,  cudaFuncAttributeMaxDynamicSharedMemorySize, SM64);
        cudaStreamCreateWithFlags(&s2, cudaStreamNonBlocking);
        cudaEventCreateWithFlags(&evF, cudaEventDisableTiming);
        cudaEventCreateWithFlags(&evJ, cudaEventDisableTiming);
    }

    // fork: CSR build + deg/adeg on side stream
    cudaEventRecord(evF, 0);
    cudaStreamWaitEvent(s2, evF, 0);
    zero_detect_kernel<<<NB, 256, 0, s2>>>((const unsigned int*)ei);
    hist_kernel<<<(EE + 255) / 256, 256, 0, s2>>>(ei);
    partial_kernel<<<NB, 256, 0, s2>>>();
    scanpart_kernel<<<1, 256, 0, s2>>>();
    offs_kernel<<<NB, 256, 0, s2>>>();
    fill_kernel<<<(EE + 255) / 256, 256, 0, s2>>>(ei);
    adeg_kernel<<<NB, 256, 0, s2>>>();
    cudaEventRecord(evJ, s2);

    // main stream: prep + GEMM1 (CSR-independent)
    const int PREP = 32768 + DOUT * DD + 2 * DD;
    prep_all_kernel<<<(PREP + 255) / 256, 256>>>(W1, W2, Wout, b1, b2);

    const int gx = (NN + 127) / 128;        // 391
    const int gg = (NN * 32 + 255) / 256;   // 6250

    gemm_k<128, 0, 0><<<gx, 256, SM128>>>(x, w1h, w1l, nullptr, nullptr, h1);  // h1 = x@W1 (fp16)

    cudaStreamWaitEvent(0, evJ, 0);   // join: CSR + deg/adeg ready

    // layer 1: relu(A^2(xW1)W1 + adeg*(b1W1) + deg*b1)
    gather_kernel<0><<<gg, 256>>>(h1, h2);                                     // h2 = A h1 (fp16)
    gather_kernel<1><<<gg, 256>>>(h2, mF);                                     // mF = A^2 (fp32)
    gemm_k<128, 1, 0><<<gx, 256, SM128>>>(mF, w1h, w1l, b1, bw1, h1);          // h1 = relu(...) fp16
    // layer 2: relu(A^2(h)W2^2 + adeg*(b2W2) + deg*b2)
    gather_kernel<0><<<gg, 256>>>(h1, h2);                                     // h2 = A h1
    gather_kernel<1><<<gg, 256>>>(h2, mF);                                     // mF = A^2 h
    gemm_k<128, 1, 1><<<gx, 256, SM128>>>(mF, w2h, w2l, b2, bw2, mG);          // mG = relu(...) fp32
    // output projection
    gemm_k<64, 2, 1><<<gx, 256, SM64>>>(mG, woh, wol, bout, nullptr, out);
}

// round 10
// speedup vs baseline: 1.3352x; 1.0431x over previous
#include <cuda_runtime.h>
#include <cuda_bf16.h>
#include <cuda_fp16.h>
#include <cstdint>

#define NN   50000
#define EE   600000
#define DD   128
#define DOUT 64
#define NB   ((NN + 255) / 256)   // 196

// ---------------- scratch ----------------
__device__ __half g_hA[(size_t)NN * DD];
__device__ __half g_hB[(size_t)NN * DD];
__device__ __nv_bfloat16 g_w1h[DD * DD], g_w1l[DD * DD];      // W1^T split
__device__ __nv_bfloat16 g_w2h[DD * DD], g_w2l[DD * DD];      // (W2^2)^T split
__device__ __nv_bfloat16 g_woh[DOUT * DD], g_wol[DOUT * DD];  // Wout^T split
__device__ float g_bw1[DD], g_bw2[DD];                        // b1@W1, b2@W2
__device__ float g_degf[NN], g_adeg[NN];
__device__ int g_deg[NN], g_cnt[NN], g_off[NN + 1];
__device__ int g_part[NB];
__device__ int g_csr[EE];
__device__ int g_is64;

__device__ __forceinline__ uint32_t smem_u32(const void* p) {
    uint32_t a;
    asm("{ .reg .u64 t; cvta.to.shared.u64 t, %1; cvt.u32.u64 %0, t; }" : "=r"(a) : "l"(p));
    return a;
}

__device__ __forceinline__ int edge_idx(const void* ei, int which, int e) {
    if (g_is64) return (int)((const long long*)ei)[(size_t)which * EE + e];
    return ((const int*)ei)[which * EE + e];
}

// ---------------- CSR build (side stream) ----------------
__global__ void zero_detect_kernel(const unsigned int* __restrict__ w) {
    int i = blockIdx.x * blockDim.x + threadIdx.x;
    if (i < NN) { g_deg[i] = 0; g_cnt[i] = 0; }
    if (i == 0) {
        int is64 = 1;
        for (int j = 1; j < 128; j += 2)
            if (w[j] != 0u) { is64 = 0; break; }
        g_is64 = is64;
    }
}
__global__ void hist_kernel(const void* ei) {
    int e = blockIdx.x * blockDim.x + threadIdx.x;
    if (e < EE) atomicAdd(&g_deg[edge_idx(ei, 1, e)], 1);
}
__global__ void partial_kernel() {
    __shared__ int sh[256];
    int t = threadIdx.x, i = blockIdx.x * 256 + t;
    sh[t] = (i < NN) ? g_deg[i] : 0;
    __syncthreads();
    for (int d = 128; d > 0; d >>= 1) {
        if (t < d) sh[t] += sh[t + d];
        __syncthreads();
    }
    if (t == 0) g_part[blockIdx.x] = sh[0];
}
// offsets: block prefix computed inline from g_part (no separate scan launch)
__global__ void offs_kernel() {
    __shared__ int sh[256];
    __shared__ int base_sh;
    int t = threadIdx.x, bid = blockIdx.x, i = bid * 256 + t;
    // sum of predecessor block aggregates (bid < 196 <= 256)
    int pv = (t < bid) ? g_part[t] : 0;
    sh[t] = pv;
    __syncthreads();
    for (int d = 128; d > 0; d >>= 1) {
        if (t < d) sh[t] += sh[t + d];
        __syncthreads();
    }
    if (t == 0) base_sh = sh[0];
    __syncthreads();
    // block-local inclusive scan of degrees
    int v = (i < NN) ? g_deg[i] : 0;
    sh[t] = v;
    __syncthreads();
    for (int d = 1; d < 256; d <<= 1) {
        int u = (t >= d) ? sh[t - d] : 0;
        __syncthreads();
        sh[t] += u;
        __syncthreads();
    }
    if (i < NN) g_off[i] = base_sh + sh[t] - v;
    if (bid == gridDim.x - 1 && t == 255) g_off[NN] = EE;
}
__global__ void fill_kernel(const void* ei) {
    int e = blockIdx.x * blockDim.x + threadIdx.x;
    if (e < EE) {
        int d = edge_idx(ei, 1, e);
        int s = edge_idx(ei, 0, e);
        g_csr[g_off[d] + atomicAdd(&g_cnt[d], 1)] = s;
    }
}
__global__ void adeg_kernel() {
    int i = blockIdx.x * blockDim.x + threadIdx.x;
    if (i >= NN) return;
    int b = g_off[i], e = g_off[i + 1];
    float s = 0.f;
    for (int k = b; k < e; k++) s += (float)g_deg[g_csr[k]];
    g_adeg[i] = s;
    g_degf[i] = (float)(e - b);
}

// ---------------- split helper ----------------
__device__ __forceinline__ void split2(float x, __nv_bfloat16& h, __nv_bfloat16& l) {
    h = __float2bfloat16(x);
    l = __float2bfloat16(x - __bfloat162float(h));
}

// ---------------- prep: W1^T split, (W2^2)^T split, Wout^T split, bW vectors ----------------
__global__ void prep_all_kernel(const float* __restrict__ W1, const float* __restrict__ W2,
                                const float* __restrict__ Wo, const float* __restrict__ b1,
                                const float* __restrict__ b2) {
    int i = blockIdx.x * blockDim.x + threadIdx.x;
    if (i < 16384) {
        int n = i >> 7, k = i & 127;
        split2(W1[k * DD + n], g_w1h[i], g_w1l[i]);
    } else if (i < 32768) {
        int j = i - 16384;
        int n = j >> 7, k = j & 127;
        float s = 0.f;
        for (int t = 0; t < DD; t++) s += W2[k * DD + t] * W2[t * DD + n];
        split2(s, g_w2h[j], g_w2l[j]);
    } else if (i < 32768 + DOUT * DD) {
        int j = i - 32768;
        int n = j >> 7, k = j & 127;
        split2(Wo[k * DOUT + n], g_woh[j], g_wol[j]);
    } else if (i < 32768 + DOUT * DD + 2 * DD) {
        int c = i - (32768 + DOUT * DD);
        if (c < DD) {
            float s = 0.f;
            for (int k = 0; k < DD; k++) s += b1[k] * W1[k * DD + c];
            g_bw1[c] = s;
        } else {
            c -= DD;
            float s = 0.f;
            for (int k = 0; k < DD; k++) s += b2[k] * W2[k * DD + c];
            g_bw2[c] = s;
        }
    }
}

// ---------------- GEMM: A inline-split (fp32 or fp16 input), 3-pass split-bf16 HMMA ----------
template <int N>
__device__ __forceinline__ void stageB(char* smem, const __nv_bfloat16* __restrict__ B, int tid) {
    for (int idx = tid; idx < N * 16; idx += 256) {
        int r = idx >> 4, ch = idx & 15;
        uint4 v = *(const uint4*)(B + r * DD + ch * 8);
        *(uint4*)(smem + 65536 + r * 256 + ((ch ^ (r & 7)) << 4)) = v;
    }
}

template <int N>
__device__ __forceinline__ void mma_pass(uint32_t sb, uint32_t aoff, float (&acc)[N / 8][4],
                                         int wid, int lane) {
    constexpr int NW = N / 2, NF16 = NW / 16, NF8 = NW / 8;
    int wr = wid & 3, wc = wid >> 2, lr = lane & 7;
    int a_half = (lane >> 3) & 1, a_kc = lane >> 4;
    int b_kc = (lane >> 3) & 1, b_nh = lane >> 4;
#pragma unroll
    for (int ks = 0; ks < 8; ks++) {
        int c0 = ks * 2;
        uint32_t a[2][4];
#pragma unroll
        for (int mf = 0; mf < 2; mf++) {
            uint32_t addr = sb + aoff + (uint32_t)((wr * 32 + mf * 16 + a_half * 8 + lr) * 256)
                          + (uint32_t)(((c0 + a_kc) ^ lr) << 4);
            asm volatile("ldmatrix.sync.aligned.m8n8.x4.shared.b16 {%0,%1,%2,%3}, [%4];"
                : "=r"(a[mf][0]), "=r"(a[mf][1]), "=r"(a[mf][2]), "=r"(a[mf][3]) : "r"(addr));
        }
#pragma unroll
        for (int nf = 0; nf < NF16; nf++) {
            uint32_t addr = sb + 65536u + (uint32_t)((wc * NW + nf * 16 + b_nh * 8 + lr) * 256)
                          + (uint32_t)(((c0 + b_kc) ^ lr) << 4);
            uint32_t b0, b1r, b2r, b3;
            asm volatile("ldmatrix.sync.aligned.m8n8.x4.shared.b16 {%0,%1,%2,%3}, [%4];"
                : "=r"(b0), "=r"(b1r), "=r"(b2r), "=r"(b3) : "r"(addr));
#pragma unroll
            for (int mf = 0; mf < 2; mf++) {
                float* c = acc[mf * NF8 + 2 * nf];
                asm volatile("mma.sync.aligned.m16n8k16.row.col.f32.bf16.bf16.f32 "
                    "{%0,%1,%2,%3}, {%4,%5,%6,%7}, {%8,%9}, {%0,%1,%2,%3};"
                    : "+f"(c[0]), "+f"(c[1]), "+f"(c[2]), "+f"(c[3])
                    : "r"(a[mf][0]), "r"(a[mf][1]), "r"(a[mf][2]), "r"(a[mf][3]), "r"(b0), "r"(b1r));
                float* d = acc[mf * NF8 + 2 * nf + 1];
                asm volatile("mma.sync.aligned.m16n8k16.row.col.f32.bf16.bf16.f32 "
                    "{%0,%1,%2,%3}, {%4,%5,%6,%7}, {%8,%9}, {%0,%1,%2,%3};"
                    : "+f"(d[0]), "+f"(d[1]), "+f"(d[2]), "+f"(d[3])
                    : "r"(a[mf][0]), "r"(a[mf][1]), "r"(a[mf][2]), "r"(a[mf][3]), "r"(b2r), "r"(b3));
            }
        }
    }
}

// INF: 0 = fp32 A, 1 = fp16 A. EPI: 0 none / 1 rowbias+relu / 2 vector bias.
// OUTF: 0 = fp16 C, 1 = fp32 C.
template <int N, int INF, int EPI, int OUTF>
__global__ void __launch_bounds__(256, 2) gemm_k(
    const void* __restrict__ Av,
    const __nv_bfloat16* __restrict__ Bhi, const __nv_bfloat16* __restrict__ Blo,
    const float* __restrict__ bias, const float* __restrict__ bw,
    void* __restrict__ Cv)
{
    extern __shared__ char smem[];
    uint32_t sb = smem_u32(smem);
    int tid = threadIdx.x, wid = tid >> 5, lane = tid & 31;
    int row0 = blockIdx.x * 128;

    // stage A hi+lo (inline split)
    for (int idx = tid; idx < 2048; idx += 256) {
        int r = idx >> 4, ch = idx & 15, grow = row0 + r;
        __nv_bfloat16 h[8], l[8];
        if (grow < NN) {
            float f[8];
            if (INF == 0) {
                const float* p = (const float*)Av + (size_t)grow * DD + ch * 8;
                float4 v0 = *(const float4*)p, v1 = *(const float4*)(p + 4);
                f[0] = v0.x; f[1] = v0.y; f[2] = v0.z; f[3] = v0.w;
                f[4] = v1.x; f[5] = v1.y; f[6] = v1.z; f[7] = v1.w;
            } else {
                const __half* p = (const __half*)Av + (size_t)grow * DD + ch * 8;
                uint4 raw = *(const uint4*)p;
                const __half2* hp = (const __half2*)&raw;
#pragma unroll
                for (int q = 0; q < 4; q++) {
                    float2 fq = __half22float2(hp[q]);
                    f[2 * q] = fq.x; f[2 * q + 1] = fq.y;
                }
            }
#pragma unroll
            for (int j = 0; j < 8; j++) split2(f[j], h[j], l[j]);
        } else {
#pragma unroll
            for (int j = 0; j < 8; j++) { h[j] = __float2bfloat16(0.f); l[j] = h[j]; }
        }
        int off = r * 256 + ((ch ^ (r & 7)) << 4);
        *(uint4*)(smem + off) = *(uint4*)h;
        *(uint4*)(smem + 32768 + off) = *(uint4*)l;
    }
    stageB<N>(smem, Bhi, tid);
    __syncthreads();

    float acc[N / 8][4];
#pragma unroll
    for (int i = 0; i < N / 8; i++)
#pragma unroll
        for (int j = 0; j < 4; j++) acc[i][j] = 0.f;

    mma_pass<N>(sb, 0u, acc, wid, lane);        // Ahi * Bhi
    mma_pass<N>(sb, 32768u, acc, wid, lane);    // Alo * Bhi
    __syncthreads();
    stageB<N>(smem, Blo, tid);
    __syncthreads();
    mma_pass<N>(sb, 0u, acc, wid, lane);        // Ahi * Blo

    // epilogue
    constexpr int NW = N / 2, NF8 = NW / 8;
    int wr = wid & 3, wc = wid >> 2;
    int g = lane >> 2, tg = lane & 3;
#pragma unroll
    for (int mf = 0; mf < 2; mf++) {
        int r = row0 + wr * 32 + mf * 16 + g;
        float d0 = 0.f, a0 = 0.f, d1 = 0.f, a1 = 0.f;
        if (EPI == 1) {
            if (r < NN)     { d0 = g_degf[r];     a0 = g_adeg[r]; }
            if (r + 8 < NN) { d1 = g_degf[r + 8]; a1 = g_adeg[r + 8]; }
        }
#pragma unroll
        for (int n8 = 0; n8 < NF8; n8++) {
            int c = wc * NW + n8 * 8 + tg * 2;
            float* v = acc[mf * NF8 + n8];
            float o0x = v[0], o0y = v[1], o1x = v[2], o1y = v[3];
            if (EPI == 1) {
                float bwx = bw[c], bwy = bw[c + 1], bx = bias[c], by = bias[c + 1];
                o0x = fmaxf(o0x + a0 * bwx + d0 * bx, 0.f);
                o0y = fmaxf(o0y + a0 * bwy + d0 * by, 0.f);
                o1x = fmaxf(o1x + a1 * bwx + d1 * bx, 0.f);
                o1y = fmaxf(o1y + a1 * bwy + d1 * by, 0.f);
            } else if (EPI == 2) {
                float bx = bias[c], by = bias[c + 1];
                o0x += bx; o0y += by; o1x += bx; o1y += by;
            }
            if (OUTF) {
                float* C = (float*)Cv;
                if (r < NN)
                    *(float2*)(C + (size_t)r * N + c) = make_float2(o0x, o0y);
                if (r + 8 < NN)
                    *(float2*)(C + (size_t)(r + 8) * N + c) = make_float2(o1x, o1y);
            } else {
                __half* C = (__half*)Cv;
                if (r < NN)
                    *(__half2*)(C + (size_t)r * N + c) = __floats2half2_rn(o0x, o0y);
                if (r + 8 < NN)
                    *(__half2*)(C + (size_t)(r + 8) * N + c) = __floats2half2_rn(o1x, o1y);
            }
        }
    }
}

// ---------------- gather-sum (warp per node, fp16 -> fp16, fp32 accumulate) ----------------
__global__ void gather_kernel(const __half* __restrict__ m, __half* __restrict__ o) {
    int gw = (blockIdx.x * blockDim.x + threadIdx.x) >> 5;
    int lane = threadIdx.x & 31;
    if (gw >= NN) return;
    int beg = g_off[gw], end = g_off[gw + 1];
    const uint2* base = (const uint2*)m;   // row = 32 x uint2 (256 B)
    float ax = 0.f, ay = 0.f, az = 0.f, aw = 0.f;
    int e = beg;
    for (; e + 8 <= end; e += 8) {
        int s[8];
#pragma unroll
        for (int i = 0; i < 8; i++) s[i] = g_csr[e + i];
        uint2 v[8];
#pragma unroll
        for (int i = 0; i < 8; i++) v[i] = base[s[i] * 32 + lane];
#pragma unroll
        for (int i = 0; i < 8; i++) {
            float2 f0 = __half22float2(*(__half2*)&v[i].x);
            float2 f1 = __half22float2(*(__half2*)&v[i].y);
            ax += f0.x; ay += f0.y; az += f1.x; aw += f1.y;
        }
    }
    for (; e < end; e++) {
        uint2 v = base[g_csr[e] * 32 + lane];
        float2 f0 = __half22float2(*(__half2*)&v.x);
        float2 f1 = __half22float2(*(__half2*)&v.y);
        ax += f0.x; ay += f0.y; az += f1.x; aw += f1.y;
    }
    uint2 r;
    *(__half2*)&r.x = __floats2half2_rn(ax, ay);
    *(__half2*)&r.y = __floats2half2_rn(az, aw);
    ((uint2*)o)[gw * 32 + lane] = r;
}

// ---------------- launch ----------------
extern "C" void kernel_launch(void* const* d_in, const int* in_sizes, int n_in,
                              void* d_out, int out_size) {
    const float* x    = (const float*)d_in[0];
    const void*  ei   = d_in[1];
    const float* W1   = (const float*)d_in[2];
    const float* b1   = (const float*)d_in[3];
    const float* W2   = (const float*)d_in[4];
    const float* b2   = (const float*)d_in[5];
    const float* Wout = (const float*)d_in[6];
    const float* bout = (const float*)d_in[7];
    float* out = (float*)d_out;

    __half *hA, *hB;
    float *bw1, *bw2;
    __nv_bfloat16 *w1h, *w1l, *w2h, *w2l, *woh, *wol;
    cudaGetSymbolAddress((void**)&hA, g_hA);
    cudaGetSymbolAddress((void**)&hB, g_hB);
    cudaGetSymbolAddress((void**)&w1h, g_w1h); cudaGetSymbolAddress((void**)&w1l, g_w1l);
    cudaGetSymbolAddress((void**)&w2h, g_w2h); cudaGetSymbolAddress((void**)&w2l, g_w2l);
    cudaGetSymbolAddress((void**)&woh, g_woh); cudaGetSymbolAddress((void**)&wol, g_wol);
    cudaGetSymbolAddress((void**)&bw1, g_bw1); cudaGetSymbolAddress((void**)&bw2, g_bw2);

    const int SM128 = 65536 + 128 * 256;   // 98304
    const int SM64  = 65536 + 64 * 256;    // 81920
    static cudaStream_t s2 = nullptr;
    static cudaEvent_t evF = nullptr, evJ = nullptr, evJ2 = nullptr;
    if (!s2) {
        cudaFuncSetAttribute((const void*)gemm_k<128, 0, 0, 0>, cudaFuncAttributeMaxDynamicSharedMemorySize, SM128);
        cudaFuncSetAttribute((const void*)gemm_k<128, 1, 1, 0>, cudaFuncAttributeMaxDynamicSharedMemorySize, SM128);
        cudaFuncSetAttribute((const void*)gemm_k<64, 1, 2, 1>,  cudaFuncAttributeMaxDynamicSharedMemorySize, SM64);
        cudaStreamCreateWithFlags(&s2, cudaStreamNonBlocking);
        cudaEventCreateWithFlags(&evF, cudaEventDisableTiming);
        cudaEventCreateWithFlags(&evJ, cudaEventDisableTiming);
        cudaEventCreateWithFlags(&evJ2, cudaEventDisableTiming);
    }

    // fork: CSR build on side stream
    cudaEventRecord(evF, 0);
    cudaStreamWaitEvent(s2, evF, 0);
    zero_detect_kernel<<<NB, 256, 0, s2>>>((const unsigned int*)ei);
    hist_kernel<<<(EE + 255) / 256, 256, 0, s2>>>(ei);
    partial_kernel<<<NB, 256, 0, s2>>>();
    offs_kernel<<<NB, 256, 0, s2>>>();
    fill_kernel<<<(EE + 255) / 256, 256, 0, s2>>>(ei);
    cudaEventRecord(evJ, s2);          // gathers need off+csr only
    adeg_kernel<<<NB, 256, 0, s2>>>();
    cudaEventRecord(evJ2, s2);         // EPI=1 gemms need adeg/degf

    // main stream: prep + GEMM1 (CSR-independent)
    const int PREP = 32768 + DOUT * DD + 2 * DD;
    prep_all_kernel<<<(PREP + 255) / 256, 256>>>(W1, W2, Wout, b1, b2);

    const int gx = (NN + 127) / 128;        // 391
    const int gg = (NN * 32 + 255) / 256;   // 6250

    gemm_k<128, 0, 0, 0><<<gx, 256, SM128>>>(x, w1h, w1l, nullptr, nullptr, hA);  // hA = x@W1 fp16

    cudaStreamWaitEvent(0, evJ, 0);    // CSR ready

    // layer 1: relu(A^2(xW1)W1 + adeg*(b1W1) + deg*b1)
    gather_kernel<<<gg, 256>>>(hA, hB);        // hB = A hA
    gather_kernel<<<gg, 256>>>(hB, hA);        // hA = A^2 (xW1)
    cudaStreamWaitEvent(0, evJ2, 0);           // adeg/degf ready (plenty of slack)
    gemm_k<128, 1, 1, 0><<<gx, 256, SM128>>>(hA, w1h, w1l, b1, bw1, hB);          // hB = relu(...)
    // layer 2: relu(A^2(h)W2^2 + adeg*(b2W2) + deg*b2)
    gather_kernel<<<gg, 256>>>(hB, hA);        // hA = A h
    gather_kernel<<<gg, 256>>>(hA, hB);        // hB = A^2 h
    gemm_k<128, 1, 1, 0><<<gx, 256, SM128>>>(hB, w2h, w2l, b2, bw2, hA);          // hA = relu(...)
    // output projection
    gemm_k<64, 1, 2, 1><<<gx, 256, SM64>>>(hA, woh, wol, bout, nullptr, out);
}

// round 11
// speedup vs baseline: 1.4293x; 1.0704x over previous
#include <cuda_runtime.h>
#include <cuda_fp16.h>
#include <cstdint>

#define NN   50000
#define EE   600000
#define DD   128
#define DOUT 64
#define NB   ((NN + 255) / 256)   // 196

// ---------------- scratch ----------------
__device__ __half g_hA[(size_t)NN * DD];
__device__ __half g_hB[(size_t)NN * DD];
__device__ __half g_w1h[DD * DD], g_w1l[DD * DD];      // W1^T fp16 split
__device__ __half g_w2h[DD * DD], g_w2l[DD * DD];      // (W2^2)^T fp16 split
__device__ __half g_woh[DOUT * DD], g_wol[DOUT * DD];  // Wout^T fp16 split
__device__ float g_bw1[DD], g_bw2[DD];                 // b1@W1, b2@W2
__device__ float g_degf[NN], g_adeg[NN];
__device__ int g_deg[NN], g_cnt[NN], g_off[NN + 1];
__device__ int g_part[NB];
__device__ int g_csr[EE];
__device__ int g_is64;

__device__ __forceinline__ uint32_t smem_u32(const void* p) {
    uint32_t a;
    asm("{ .reg .u64 t; cvta.to.shared.u64 t, %1; cvt.u32.u64 %0, t; }" : "=r"(a) : "l"(p));
    return a;
}

__device__ __forceinline__ int edge_idx(const void* ei, int which, int e) {
    if (g_is64) return (int)((const long long*)ei)[(size_t)which * EE + e];
    return ((const int*)ei)[which * EE + e];
}

// ---------------- CSR build (side stream) ----------------
__global__ void zero_detect_kernel(const unsigned int* __restrict__ w) {
    int i = blockIdx.x * blockDim.x + threadIdx.x;
    if (i < NN) { g_deg[i] = 0; g_cnt[i] = 0; }
    if (i == 0) {
        int is64 = 1;
        for (int j = 1; j < 128; j += 2)
            if (w[j] != 0u) { is64 = 0; break; }
        g_is64 = is64;
    }
}
__global__ void hist_kernel(const void* ei) {
    int e = blockIdx.x * blockDim.x + threadIdx.x;
    if (e < EE) atomicAdd(&g_deg[edge_idx(ei, 1, e)], 1);
}
__global__ void partial_kernel() {
    __shared__ int sh[256];
    int t = threadIdx.x, i = blockIdx.x * 256 + t;
    sh[t] = (i < NN) ? g_deg[i] : 0;
    __syncthreads();
    for (int d = 128; d > 0; d >>= 1) {
        if (t < d) sh[t] += sh[t + d];
        __syncthreads();
    }
    if (t == 0) g_part[blockIdx.x] = sh[0];
}
__global__ void offs_kernel() {
    __shared__ int sh[256];
    __shared__ int base_sh;
    int t = threadIdx.x, bid = blockIdx.x, i = bid * 256 + t;
    int pv = (t < bid) ? g_part[t] : 0;
    sh[t] = pv;
    __syncthreads();
    for (int d = 128; d > 0; d >>= 1) {
        if (t < d) sh[t] += sh[t + d];
        __syncthreads();
    }
    if (t == 0) base_sh = sh[0];
    __syncthreads();
    int v = (i < NN) ? g_deg[i] : 0;
    sh[t] = v;
    __syncthreads();
    for (int d = 1; d < 256; d <<= 1) {
        int u = (t >= d) ? sh[t - d] : 0;
        __syncthreads();
        sh[t] += u;
        __syncthreads();
    }
    if (i < NN) g_off[i] = base_sh + sh[t] - v;
    if (bid == gridDim.x - 1 && t == 255) g_off[NN] = EE;
}
__global__ void fill_kernel(const void* ei) {
    int e = blockIdx.x * blockDim.x + threadIdx.x;
    if (e < EE) {
        int d = edge_idx(ei, 1, e);
        int s = edge_idx(ei, 0, e);
        g_csr[g_off[d] + atomicAdd(&g_cnt[d], 1)] = s;
    }
}
__global__ void adeg_kernel() {
    int i = blockIdx.x * blockDim.x + threadIdx.x;
    if (i >= NN) return;
    int b = g_off[i], e = g_off[i + 1];
    float s = 0.f;
    for (int k = b; k < e; k++) s += (float)g_deg[g_csr[k]];
    g_adeg[i] = s;
    g_degf[i] = (float)(e - b);
}

// ---------------- fp16 split helper ----------------
__device__ __forceinline__ void split2h(float x, __half& h, __half& l) {
    h = __float2half(x);
    l = __float2half(x - __half2float(h));
}

// ---------------- prep: W1^T, (W2^2)^T, Wout^T fp16 splits + bW vectors ----------------
__global__ void prep_all_kernel(const float* __restrict__ W1, const float* __restrict__ W2,
                                const float* __restrict__ Wo, const float* __restrict__ b1,
                                const float* __restrict__ b2) {
    int i = blockIdx.x * blockDim.x + threadIdx.x;
    if (i < 16384) {
        int n = i >> 7, k = i & 127;
        split2h(W1[k * DD + n], g_w1h[i], g_w1l[i]);
    } else if (i < 32768) {
        int j = i - 16384;
        int n = j >> 7, k = j & 127;
        float s = 0.f;
        for (int t = 0; t < DD; t++) s += W2[k * DD + t] * W2[t * DD + n];
        split2h(s, g_w2h[j], g_w2l[j]);
    } else if (i < 32768 + DOUT * DD) {
        int j = i - 32768;
        int n = j >> 7, k = j & 127;
        split2h(Wo[k * DOUT + n], g_woh[j], g_wol[j]);
    } else if (i < 32768 + DOUT * DD + 2 * DD) {
        int c = i - (32768 + DOUT * DD);
        if (c < DD) {
            float s = 0.f;
            for (int k = 0; k < DD; k++) s += b1[k] * W1[k * DD + c];
            g_bw1[c] = s;
        } else {
            c -= DD;
            float s = 0.f;
            for (int k = 0; k < DD; k++) s += b2[k] * W2[k * DD + c];
            g_bw2[c] = s;
        }
    }
}

// ---------------- fp16 MMA core ----------------
// A plane at sb+aoff, B plane at sb+boff (both swizzled 256B-row layout)
template <int N>
__device__ __forceinline__ void mma_pass(uint32_t sb, uint32_t aoff, uint32_t boff,
                                         float (&acc)[N / 8][4], int wid, int lane) {
    constexpr int NW = N / 2, NF16 = NW / 16, NF8 = NW / 8;
    int wr = wid & 3, wc = wid >> 2, lr = lane & 7;
    int a_half = (lane >> 3) & 1, a_kc = lane >> 4;
    int b_kc = (lane >> 3) & 1, b_nh = lane >> 4;
#pragma unroll
    for (int ks = 0; ks < 8; ks++) {
        int c0 = ks * 2;
        uint32_t a[2][4];
#pragma unroll
        for (int mf = 0; mf < 2; mf++) {
            uint32_t addr = sb + aoff + (uint32_t)((wr * 32 + mf * 16 + a_half * 8 + lr) * 256)
                          + (uint32_t)(((c0 + a_kc) ^ lr) << 4);
            asm volatile("ldmatrix.sync.aligned.m8n8.x4.shared.b16 {%0,%1,%2,%3}, [%4];"
                : "=r"(a[mf][0]), "=r"(a[mf][1]), "=r"(a[mf][2]), "=r"(a[mf][3]) : "r"(addr));
        }
#pragma unroll
        for (int nf = 0; nf < NF16; nf++) {
            uint32_t addr = sb + boff + (uint32_t)((wc * NW + nf * 16 + b_nh * 8 + lr) * 256)
                          + (uint32_t)(((c0 + b_kc) ^ lr) << 4);
            uint32_t b0, b1r, b2r, b3;
            asm volatile("ldmatrix.sync.aligned.m8n8.x4.shared.b16 {%0,%1,%2,%3}, [%4];"
                : "=r"(b0), "=r"(b1r), "=r"(b2r), "=r"(b3) : "r"(addr));
#pragma unroll
            for (int mf = 0; mf < 2; mf++) {
                float* c = acc[mf * NF8 + 2 * nf];
                asm volatile("mma.sync.aligned.m16n8k16.row.col.f32.f16.f16.f32 "
                    "{%0,%1,%2,%3}, {%4,%5,%6,%7}, {%8,%9}, {%0,%1,%2,%3};"
                    : "+f"(c[0]), "+f"(c[1]), "+f"(c[2]), "+f"(c[3])
                    : "r"(a[mf][0]), "r"(a[mf][1]), "r"(a[mf][2]), "r"(a[mf][3]), "r"(b0), "r"(b1r));
                float* d = acc[mf * NF8 + 2 * nf + 1];
                asm volatile("mma.sync.aligned.m16n8k16.row.col.f32.f16.f16.f32 "
                    "{%0,%1,%2,%3}, {%4,%5,%6,%7}, {%8,%9}, {%0,%1,%2,%3};"
                    : "+f"(d[0]), "+f"(d[1]), "+f"(d[2]), "+f"(d[3])
                    : "r"(a[mf][0]), "r"(a[mf][1]), "r"(a[mf][2]), "r"(a[mf][3]), "r"(b2r), "r"(b3));
            }
        }
    }
}

template <int N>
__device__ __forceinline__ void stageB_at(char* smem, uint32_t boff,
                                          const __half* __restrict__ B, int tid) {
    for (int idx = tid; idx < N * 16; idx += 256) {
        int r = idx >> 4, ch = idx & 15;
        uint4 v = *(const uint4*)(B + r * DD + ch * 8);
        *(uint4*)(smem + boff + r * 256 + ((ch ^ (r & 7)) << 4)) = v;
    }
}

// epilogue shared by both gemm kernels
template <int N, int EPI, int OUTF>
__device__ __forceinline__ void epilogue(float (&acc)[N / 8][4],
                                         const float* __restrict__ bias,
                                         const float* __restrict__ bw,
                                         void* __restrict__ Cv, int row0,
                                         int wid, int lane) {
    constexpr int NW = N / 2, NF8 = NW / 8;
    int wr = wid & 3, wc = wid >> 2;
    int g = lane >> 2, tg = lane & 3;
#pragma unroll
    for (int mf = 0; mf < 2; mf++) {
        int r = row0 + wr * 32 + mf * 16 + g;
        float d0 = 0.f, a0 = 0.f, d1 = 0.f, a1 = 0.f;
        if (EPI == 1) {
            if (r < NN)     { d0 = g_degf[r];     a0 = g_adeg[r]; }
            if (r + 8 < NN) { d1 = g_degf[r + 8]; a1 = g_adeg[r + 8]; }
        }
#pragma unroll
        for (int n8 = 0; n8 < NF8; n8++) {
            int c = wc * NW + n8 * 8 + tg * 2;
            float* v = acc[mf * NF8 + n8];
            float o0x = v[0], o0y = v[1], o1x = v[2], o1y = v[3];
            if (EPI == 1) {
                float bwx = bw[c], bwy = bw[c + 1], bx = bias[c], by = bias[c + 1];
                o0x = fmaxf(o0x + a0 * bwx + d0 * bx, 0.f);
                o0y = fmaxf(o0y + a0 * bwy + d0 * by, 0.f);
                o1x = fmaxf(o1x + a1 * bwx + d1 * bx, 0.f);
                o1y = fmaxf(o1y + a1 * bwy + d1 * by, 0.f);
            } else if (EPI == 2) {
                float bx = bias[c], by = bias[c + 1];
                o0x += bx; o0y += by; o1x += bx; o1y += by;
            }
            if (OUTF) {
                float* C = (float*)Cv;
                if (r < NN)
                    *(float2*)(C + (size_t)r * N + c) = make_float2(o0x, o0y);
                if (r + 8 < NN)
                    *(float2*)(C + (size_t)(r + 8) * N + c) = make_float2(o1x, o1y);
            } else {
                __half* C = (__half*)Cv;
                if (r < NN)
                    *(__half2*)(C + (size_t)r * N + c) = __floats2half2_rn(o0x, o0y);
                if (r + 8 < NN)
                    *(__half2*)(C + (size_t)(r + 8) * N + c) = __floats2half2_rn(o1x, o1y);
            }
        }
    }
}

// ---------------- on-path GEMM: A fp16 native (1 plane), B fp16 hi+lo (2 passes) ----------
// smem: A [0,32K), Bhi [32K, 32K+N*256), Blo [32K+N*256, 32K+2*N*256)
template <int N, int EPI, int OUTF>
__global__ void __launch_bounds__(256, 2) gemm_on(
    const __half* __restrict__ A,
    const __half* __restrict__ Bhi, const __half* __restrict__ Blo,
    const float* __restrict__ bias, const float* __restrict__ bw,
    void* __restrict__ Cv)
{
    extern __shared__ char smem[];
    uint32_t sb = smem_u32(smem);
    int tid = threadIdx.x, wid = tid >> 5, lane = tid & 31;
    int row0 = blockIdx.x * 128;

    // stage A: raw fp16 copy into swizzled layout
    for (int idx = tid; idx < 2048; idx += 256) {
        int r = idx >> 4, ch = idx & 15, grow = row0 + r;
        uint4 v = make_uint4(0, 0, 0, 0);
        if (grow < NN) v = *(const uint4*)(A + (size_t)grow * DD + ch * 8);
        *(uint4*)(smem + r * 256 + ((ch ^ (r & 7)) << 4)) = v;
    }
    stageB_at<N>(smem, 32768u, Bhi, tid);
    stageB_at<N>(smem, 32768u + N * 256, Blo, tid);
    __syncthreads();

    float acc[N / 8][4];
#pragma unroll
    for (int i = 0; i < N / 8; i++)
#pragma unroll
        for (int j = 0; j < 4; j++) acc[i][j] = 0.f;

    mma_pass<N>(sb, 0u, 32768u, acc, wid, lane);             // A * Bhi
    mma_pass<N>(sb, 0u, 32768u + N * 256, acc, wid, lane);   // A * Blo

    epilogue<N, EPI, OUTF>(acc, bias, bw, Cv, row0, wid, lane);
}

// ---------------- head GEMM: fp32 X, fp16-split A (3 passes) ----------------
// smem: Ahi [0,32K), Alo [32K,64K), B [64K,96K)
__global__ void __launch_bounds__(256, 2) gemm_x(
    const float* __restrict__ X,
    const __half* __restrict__ Bhi, const __half* __restrict__ Blo,
    void* __restrict__ Cv)
{
    extern __shared__ char smem[];
    constexpr int N = 128;
    uint32_t sb = smem_u32(smem);
    int tid = threadIdx.x, wid = tid >> 5, lane = tid & 31;
    int row0 = blockIdx.x * 128;

    for (int idx = tid; idx < 2048; idx += 256) {
        int r = idx >> 4, ch = idx & 15, grow = row0 + r;
        __half h[8], l[8];
        if (grow < NN) {
            const float* p = X + (size_t)grow * DD + ch * 8;
            float4 v0 = *(const float4*)p, v1 = *(const float4*)(p + 4);
            float f[8] = {v0.x, v0.y, v0.z, v0.w, v1.x, v1.y, v1.z, v1.w};
#pragma unroll
            for (int j = 0; j < 8; j++) split2h(f[j], h[j], l[j]);
        } else {
#pragma unroll
            for (int j = 0; j < 8; j++) { h[j] = __float2half(0.f); l[j] = h[j]; }
        }
        int off = r * 256 + ((ch ^ (r & 7)) << 4);
        *(uint4*)(smem + off) = *(uint4*)h;
        *(uint4*)(smem + 32768 + off) = *(uint4*)l;
    }
    stageB_at<N>(smem, 65536u, Bhi, tid);
    __syncthreads();

    float acc[N / 8][4];
#pragma unroll
    for (int i = 0; i < N / 8; i++)
#pragma unroll
        for (int j = 0; j < 4; j++) acc[i][j] = 0.f;

    mma_pass<N>(sb, 0u, 65536u, acc, wid, lane);       // Ahi * Bhi
    mma_pass<N>(sb, 32768u, 65536u, acc, wid, lane);   // Alo * Bhi
    __syncthreads();
    stageB_at<N>(smem, 65536u, Blo, tid);
    __syncthreads();
    mma_pass<N>(sb, 0u, 65536u, acc, wid, lane);       // Ahi * Blo

    epilogue<N, 0, 0>(acc, nullptr, nullptr, Cv, row0, wid, lane);
}

// ---------------- gather: warp/node, 16 lanes x 16B per row, 2 edges per step ----------------
__global__ void gather_kernel(const __half* __restrict__ m, __half* __restrict__ o) {
    int gw = (blockIdx.x * blockDim.x + threadIdx.x) >> 5;
    int lane = threadIdx.x & 31;
    if (gw >= NN) return;
    int beg = g_off[gw], end = g_off[gw + 1];
    int h = lane >> 4, cl = lane & 15;
    const uint4* base = (const uint4*)m;   // row = 16 x uint4 (256 B)
    float acc[8];
#pragma unroll
    for (int j = 0; j < 8; j++) acc[j] = 0.f;

    int e = beg + h;
    // 4 edges per half-warp per iteration (stride 2)
    for (; e + 6 < end; e += 8) {
        int s0 = g_csr[e], s1 = g_csr[e + 2], s2 = g_csr[e + 4], s3 = g_csr[e + 6];
        uint4 v0 = base[s0 * 16 + cl];
        uint4 v1 = base[s1 * 16 + cl];
        uint4 v2 = base[s2 * 16 + cl];
        uint4 v3 = base[s3 * 16 + cl];
        const uint4* vv[4] = {&v0, &v1, &v2, &v3};
#pragma unroll
        for (int q = 0; q < 4; q++) {
            const __half2* hp = (const __half2*)vv[q];
#pragma unroll
            for (int j = 0; j < 4; j++) {
                float2 f = __half22float2(hp[j]);
                acc[2 * j] += f.x; acc[2 * j + 1] += f.y;
            }
        }
    }
    for (; e < end; e += 2) {
        uint4 v = base[g_csr[e] * 16 + cl];
        const __half2* hp = (const __half2*)&v;
#pragma unroll
        for (int j = 0; j < 4; j++) {
            float2 f = __half22float2(hp[j]);
            acc[2 * j] += f.x; acc[2 * j + 1] += f.y;
        }
    }
    // combine the two half-warps (all 32 lanes active: gw is warp-uniform)
#pragma unroll
    for (int j = 0; j < 8; j++)
        acc[j] += __shfl_xor_sync(0xffffffffu, acc[j], 16);
    if (h == 0) {
        uint4 r;
        ((__half2*)&r)[0] = __floats2half2_rn(acc[0], acc[1]);
        ((__half2*)&r)[1] = __floats2half2_rn(acc[2], acc[3]);
        ((__half2*)&r)[2] = __floats2half2_rn(acc[4], acc[5]);
        ((__half2*)&r)[3] = __floats2half2_rn(acc[6], acc[7]);
        ((uint4*)o)[gw * 16 + cl] = r;
    }
}

// ---------------- launch ----------------
extern "C" void kernel_launch(void* const* d_in, const int* in_sizes, int n_in,
                              void* d_out, int out_size) {
    const float* x    = (const float*)d_in[0];
    const void*  ei   = d_in[1];
    const float* W1   = (const float*)d_in[2];
    const float* b1   = (const float*)d_in[3];
    const float* W2   = (const float*)d_in[4];
    const float* b2   = (const float*)d_in[5];
    const float* Wout = (const float*)d_in[6];
    const float* bout = (const float*)d_in[7];
    float* out = (float*)d_out;

    __half *hA, *hB, *w1h, *w1l, *w2h, *w2l, *woh, *wol;
    float *bw1, *bw2;
    cudaGetSymbolAddress((void**)&hA, g_hA);
    cudaGetSymbolAddress((void**)&hB, g_hB);
    cudaGetSymbolAddress((void**)&w1h, g_w1h); cudaGetSymbolAddress((void**)&w1l, g_w1l);
    cudaGetSymbolAddress((void**)&w2h, g_w2h); cudaGetSymbolAddress((void**)&w2l, g_w2l);
    cudaGetSymbolAddress((void**)&woh, g_woh); cudaGetSymbolAddress((void**)&wol, g_wol);
    cudaGetSymbolAddress((void**)&bw1, g_bw1); cudaGetSymbolAddress((void**)&bw2, g_bw2);

    const int SMX   = 98304;                  // gemm_x: 64K A planes + 32K B
    const int SM128 = 32768 + 2 * 128 * 256;  // 98304
    const int SM64  = 32768 + 2 * 64 * 256;   // 65536
    static cudaStream_t s2 = nullptr;
    static cudaEvent_t evF = nullptr, evJ = nullptr, evJ2 = nullptr;
    if (!s2) {
        cudaFuncSetAttribute((const void*)gemm_x, cudaFuncAttributeMaxDynamicSharedMemorySize, SMX);
        cudaFuncSetAttribute((const void*)gemm_on<128, 1, 0>, cudaFuncAttributeMaxDynamicSharedMemorySize, SM128);
        cudaFuncSetAttribute((const void*)gemm_on<64, 2, 1>,  cudaFuncAttributeMaxDynamicSharedMemorySize, SM64);
        cudaStreamCreateWithFlags(&s2, cudaStreamNonBlocking);
        cudaEventCreateWithFlags(&evF, cudaEventDisableTiming);
        cudaEventCreateWithFlags(&evJ, cudaEventDisableTiming);
        cudaEventCreateWithFlags(&evJ2, cudaEventDisableTiming);
    }

    // fork: CSR build on side stream
    cudaEventRecord(evF, 0);
    cudaStreamWaitEvent(s2, evF, 0);
    zero_detect_kernel<<<NB, 256, 0, s2>>>((const unsigned int*)ei);
    hist_kernel<<<(EE + 255) / 256, 256, 0, s2>>>(ei);
    partial_kernel<<<NB, 256, 0, s2>>>();
    offs_kernel<<<NB, 256, 0, s2>>>();
    fill_kernel<<<(EE + 255) / 256, 256, 0, s2>>>(ei);
    cudaEventRecord(evJ, s2);          // gathers need off+csr only
    adeg_kernel<<<NB, 256, 0, s2>>>();
    cudaEventRecord(evJ2, s2);         // EPI=1 gemms need adeg/degf

    // main stream: prep + head GEMM (CSR-independent)
    const int PREP = 32768 + DOUT * DD + 2 * DD;
    prep_all_kernel<<<(PREP + 255) / 256, 256>>>(W1, W2, Wout, b1, b2);

    const int gx = (NN + 127) / 128;        // 391
    const int gg = (NN * 32 + 255) / 256;   // 6250

    gemm_x<<<gx, 256, SMX>>>(x, w1h, w1l, hA);   // hA = x@W1 (fp16)

    cudaStreamWaitEvent(0, evJ, 0);    // CSR ready

    // layer 1: relu(A^2(xW1)W1 + adeg*(b1W1) + deg*b1)
    gather_kernel<<<gg, 256>>>(hA, hB);        // hB = A hA
    gather_kernel<<<gg, 256>>>(hB, hA);        // hA = A^2 (xW1)
    cudaStreamWaitEvent(0, evJ2, 0);           // adeg/degf ready
    gemm_on<128, 1, 0><<<gx, 256, SM128>>>(hA, w1h, w1l, b1, bw1, hB);
    // layer 2: relu(A^2(h)W2^2 + adeg*(b2W2) + deg*b2)
    gather_kernel<<<gg, 256>>>(hB, hA);        // hA = A h
    gather_kernel<<<gg, 256>>>(hA, hB);        // hB = A^2 h
    gemm_on<128, 1, 0><<<gx, 256, SM128>>>(hB, w2h, w2l, b2, bw2, hA);
    // output projection
    gemm_on<64, 2, 1><<<gx, 256, SM64>>>(hA, woh, wol, bout, nullptr, out);
}